// round 9
// baseline (speedup 1.0000x reference)
#include <cuda_runtime.h>
#include <cuda_bf16.h>
#include <cstdint>

// CapsNet dynamic routing, single persistent kernel (144 resident CTAs,
// software grid barrier). u_hat never materialized; bf16 hi/lo 3-pass GEMMs
// on mma.sync (m16n8k16, fp32 accum).
//   inp: [256,1152,8] fp32, W: [1152,10,16,8] fp32, out v: [256,10,16] fp32
//
// All __device__ globals referenced only inside device code (host-passed
// __device__ symbols silently resolve to ATS host memory on GB300).

#define BATCH   256
#define INCH    1152
#define INU     8
#define OUTCH   10
#define OUTU    16
#define KDIM    (INCH*INU)     // 9216
#define NDIM    (OUTCH*OUTU)   // 160
#define NCHUNK  144            // 64-k chunks (8 capsules each)
#define SPLITS_S 36            // s-GEMM K splits (4 chunks = 256 K per CTA)
#define GRID    144
#define THREADS 256

// ---------------- device globals ----------------
__device__ __nv_bfloat16 g_inp_hi[BATCH * KDIM];
__device__ __nv_bfloat16 g_inp_lo[BATCH * KDIM];
__device__ __nv_bfloat16 g_inpT_hi[KDIM * BATCH];
__device__ __nv_bfloat16 g_inpT_lo[KDIM * BATCH];
__device__ __nv_bfloat16 g_vT_hi[NDIM * BATCH];
__device__ __nv_bfloat16 g_vT_lo[NDIM * BATCH];
__device__ __nv_bfloat16 g_Bt_hi[NCHUNK * NDIM * 64];  // chunk-tiled Wc
__device__ __nv_bfloat16 g_Bt_lo[NCHUNK * NDIM * 64];
__device__ float g_part_s[SPLITS_S * BATCH * NDIM];    // 5.9 MB
__device__ float g_b[INCH * OUTCH];
__device__ unsigned g_bar;                              // grid barrier counter

__device__ __forceinline__ uint32_t smem_to_u32(const void* p) {
    uint32_t a;
    asm("{ .reg .u64 t; cvta.to.shared.u64 t, %1; cvt.u32.u64 %0, t; }"
        : "=r"(a) : "l"(p));
    return a;
}
__device__ __forceinline__ void split_bf16(float x, __nv_bfloat16& h, __nv_bfloat16& l) {
    h = __float2bfloat16(x);
    l = __float2bfloat16(x - __bfloat162float(h));
}
__device__ __forceinline__ void ldsm4(uint32_t& r0, uint32_t& r1, uint32_t& r2,
                                      uint32_t& r3, uint32_t addr) {
    asm volatile("ldmatrix.sync.aligned.m8n8.x4.shared.b16 {%0,%1,%2,%3}, [%4];"
                 : "=r"(r0), "=r"(r1), "=r"(r2), "=r"(r3) : "r"(addr));
}
__device__ __forceinline__ void mma16816(float* d, const uint32_t* a,
                                         const uint32_t* b) {
    asm volatile(
        "mma.sync.aligned.m16n8k16.row.col.f32.bf16.bf16.f32 "
        "{%0,%1,%2,%3}, {%4,%5,%6,%7}, {%8,%9}, {%0,%1,%2,%3};"
        : "+f"(d[0]), "+f"(d[1]), "+f"(d[2]), "+f"(d[3])
        : "r"(a[0]), "r"(a[1]), "r"(a[2]), "r"(a[3]), "r"(b[0]), "r"(b[1]));
}
__device__ __forceinline__ void cp16(uint32_t dst, const void* src) {
    asm volatile("cp.async.cg.shared.global [%0], [%1], 16;"
                 :: "r"(dst), "l"(src));
}
__device__ __forceinline__ void cp_commit() {
    asm volatile("cp.async.commit_group;");
}
template <int N>
__device__ __forceinline__ void cp_wait() {
    asm volatile("cp.async.wait_group %0;" :: "n"(N));
}

// Grid barrier: monotonic counter (reset by conv_inp each harness call).
__device__ __forceinline__ void gbar(int n) {
    __syncthreads();
    if (threadIdx.x == 0) {
        __threadfence();
        atomicAdd(&g_bar, 1u);
        unsigned tgt = (unsigned)n * GRID;
        while (atomicAdd(&g_bar, 0u) < tgt) __nanosleep(32);
        __threadfence();
    }
    __syncthreads();
}

// ---------------------------------------------------------------------------
// One-time: inp fp32 -> bf16 hi/lo, plus transposed copies. Resets g_bar.
// ---------------------------------------------------------------------------
__global__ void conv_inp(const float* __restrict__ inp) {
    if (blockIdx.x == 0 && blockIdx.y == 0 && threadIdx.x == 0 && threadIdx.y == 0)
        g_bar = 0;
    __shared__ __nv_bfloat16 sh_hi[32][33];
    __shared__ __nv_bfloat16 sh_lo[32][33];
    int ik0 = blockIdx.x * 32, b0 = blockIdx.y * 32;
    int tx = threadIdx.x, ty = threadIdx.y;
    #pragma unroll
    for (int j = 0; j < 4; j++) {
        int bl = ty + 8 * j;
        float x = inp[(size_t)(b0 + bl) * KDIM + ik0 + tx];
        __nv_bfloat16 h, l;
        split_bf16(x, h, l);
        g_inp_hi[(size_t)(b0 + bl) * KDIM + ik0 + tx] = h;
        g_inp_lo[(size_t)(b0 + bl) * KDIM + ik0 + tx] = l;
        sh_hi[tx][bl] = h;
        sh_lo[tx][bl] = l;
    }
    __syncthreads();
    #pragma unroll
    for (int j = 0; j < 4; j++) {
        int ikl = ty + 8 * j;
        g_inpT_hi[(size_t)(ik0 + ikl) * BATCH + b0 + tx] = sh_hi[ikl][tx];
        g_inpT_lo[(size_t)(ik0 + ikl) * BATCH + b0 + tx] = sh_lo[ikl][tx];
    }
}

// ---------------------------------------------------------------------------
// Fused persistent kernel. Shared one-shot staging layout (224 KB):
//   AH: 4 chunks x 64 rows x 128 B  = 32 KB      at 0
//   AL: 32 KB                                    at 32768
//   BH: 4 chunks x 160 rows x 128 B = 80 KB      at 65536
//   BL: 80 KB                                    at 147456
// Swizzle: col16 ^= row&7 (applied at cp.async write and ldmatrix read).
// ---------------------------------------------------------------------------
#define SG_AH 0
#define SG_AL 32768
#define SG_BH 65536
#define SG_BL 147456
#define SG_TOT 229376

__device__ __forceinline__ uint32_t swz(uint32_t base, int row, int col16) {
    return base + (uint32_t)row * 128 + (uint32_t)((col16 ^ (row & 7)) << 4);
}

__global__ void __launch_bounds__(THREADS, 1)
fused(const float* __restrict__ W, float* __restrict__ out) {
    extern __shared__ char sm[];
    __shared__ float c_s[8][10];
    uint32_t sb = smem_to_u32(sm);
    int cta = blockIdx.x;
    int tid = threadIdx.x, lane = tid & 31, wid = tid >> 5;
    int warp_m = wid & 3, warp_n = wid >> 2;

    // ldmatrix lane address components
    int a_row_l = ((lane >> 3) & 1) * 8 + (lane & 7);
    int a_c16_l = lane >> 4;
    int b_dn_l  = ((lane >> 4) & 1) * 8 + (lane & 7);
    int b_c16_l = (lane >> 3) & 1;

    int bar_n = 0;

    for (int t = 0; t < 3; t++) {
        // ================= Phase 1: Wc build (cta == chunk) ================
        {
            int chunk = cta, i0 = chunk * 8;
            if (tid < 8) {
                int i = i0 + tid;
                if (t == 0) {
                    #pragma unroll
                    for (int o = 0; o < OUTCH; o++) c_s[tid][o] = 0.1f;
                } else {
                    float bv[OUTCH], m = -1e30f;
                    #pragma unroll
                    for (int o = 0; o < OUTCH; o++) {
                        bv[o] = g_b[i * OUTCH + o];
                        m = fmaxf(m, bv[o]);
                    }
                    float sum = 0.f;
                    #pragma unroll
                    for (int o = 0; o < OUTCH; o++) { bv[o] = expf(bv[o] - m); sum += bv[o]; }
                    float inv = 1.0f / sum;
                    #pragma unroll
                    for (int o = 0; o < OUTCH; o++) c_s[tid][o] = bv[o] * inv;
                }
            }
            __syncthreads();
            const float4* W4 = (const float4*)(W + (size_t)i0 * 1280);
            __nv_bfloat16* bh = g_Bt_hi + (size_t)chunk * (NDIM * 64);
            __nv_bfloat16* bl = g_Bt_lo + (size_t)chunk * (NDIM * 64);
            #pragma unroll
            for (int r = 0; r < 10; r++) {
                int q = tid + (r << 8);
                int i_off = q / 320;
                int rem = q - i_off * 320;
                int o = rem >> 5;
                int rem2 = rem & 31;
                int u = rem2 >> 1, kh = rem2 & 1;
                float4 f = W4[q];
                float cv = c_s[i_off][o];
                __nv_bfloat16 h0,l0,h1,l1,h2,l2,h3,l3;
                split_bf16(f.x * cv, h0, l0);
                split_bf16(f.y * cv, h1, l1);
                split_bf16(f.z * cv, h2, l2);
                split_bf16(f.w * cv, h3, l3);
                uint2 ph, pl;
                ph.x = (uint32_t)__bfloat16_as_ushort(h0) | ((uint32_t)__bfloat16_as_ushort(h1) << 16);
                ph.y = (uint32_t)__bfloat16_as_ushort(h2) | ((uint32_t)__bfloat16_as_ushort(h3) << 16);
                pl.x = (uint32_t)__bfloat16_as_ushort(l0) | ((uint32_t)__bfloat16_as_ushort(l1) << 16);
                pl.y = (uint32_t)__bfloat16_as_ushort(l2) | ((uint32_t)__bfloat16_as_ushort(l3) << 16);
                int off = (o * 16 + u) * 64 + i_off * 8 + kh * 4;
                *(uint2*)(bh + off) = ph;
                *(uint2*)(bl + off) = pl;
            }
        }
        gbar(++bar_n);

        // ================= Phase 2: s-GEMM (cta -> 4 Mtiles x 36 Ksplits) ==
        {
            int bx = cta & 3, by = cta >> 2;
            int m0 = bx * 64;
            int chunk0 = by * 4;

            #pragma unroll
            for (int c = 0; c < 4; c++) {
                int kb = (chunk0 + c) * 64;
                #pragma unroll
                for (int r = 0; r < 2; r++) {
                    int e = tid + (r << 8);
                    int row = e >> 3, j = e & 7;
                    cp16(sb + swz(SG_AH + c * 8192, row, j),
                         g_inp_hi + (size_t)(m0 + row) * KDIM + kb + j * 8);
                }
                #pragma unroll
                for (int r = 0; r < 5; r++) {
                    int e = tid + (r << 8);
                    int row = e >> 3, j = e & 7;
                    cp16(sb + swz(SG_BH + c * 20480, row, j),
                         g_Bt_hi + (size_t)(chunk0 + c) * (NDIM * 64) + e * 8);
                }
                cp_commit();
            }
            #pragma unroll
            for (int c = 0; c < 4; c++) {
                #pragma unroll
                for (int r = 0; r < 5; r++) {
                    int e = tid + (r << 8);
                    int row = e >> 3, j = e & 7;
                    cp16(sb + swz(SG_BL + c * 20480, row, j),
                         g_Bt_lo + (size_t)(chunk0 + c) * (NDIM * 64) + e * 8);
                }
                cp_commit();
            }
            #pragma unroll
            for (int c = 0; c < 4; c++) {
                int kb = (chunk0 + c) * 64;
                #pragma unroll
                for (int r = 0; r < 2; r++) {
                    int e = tid + (r << 8);
                    int row = e >> 3, j = e & 7;
                    cp16(sb + swz(SG_AL + c * 8192, row, j),
                         g_inp_lo + (size_t)(m0 + row) * KDIM + kb + j * 8);
                }
                cp_commit();
            }

            float acc[10][4];
            #pragma unroll
            for (int nt = 0; nt < 10; nt++)
                #pragma unroll
                for (int r = 0; r < 4; r++) acc[nt][r] = 0.f;

            auto do_chunk = [&](uint32_t aBase, uint32_t bBase) {
                #pragma unroll
                for (int ks = 0; ks < 4; ks++) {
                    uint32_t af[4], bf[10][2];
                    int arow = warp_m * 16 + a_row_l;
                    ldsm4(af[0], af[1], af[2], af[3],
                          sb + swz(aBase, arow, (ks << 1) | a_c16_l));
                    #pragma unroll
                    for (int p = 0; p < 5; p++) {
                        int brow = warp_n * 80 + p * 16 + b_dn_l;
                        ldsm4(bf[2*p][0], bf[2*p][1], bf[2*p+1][0], bf[2*p+1][1],
                              sb + swz(bBase, brow, (ks << 1) | b_c16_l));
                    }
                    #pragma unroll
                    for (int nt = 0; nt < 10; nt++)
                        mma16816(acc[nt], af, bf[nt]);
                }
            };

            cp_wait<8>();
            __syncthreads();
            #pragma unroll
            for (int c = 0; c < 4; c++)
                do_chunk(SG_AH + c * 8192, SG_BH + c * 20480);
            cp_wait<4>();
            __syncthreads();
            #pragma unroll
            for (int c = 0; c < 4; c++)
                do_chunk(SG_AH + c * 8192, SG_BL + c * 20480);
            cp_wait<0>();
            __syncthreads();
            #pragma unroll
            for (int c = 0; c < 4; c++)
                do_chunk(SG_AL + c * 8192, SG_BH + c * 20480);

            float* po = g_part_s + (size_t)by * (BATCH * NDIM);
            int r_l = lane >> 2, c_l = (lane & 3) * 2;
            int row = m0 + warp_m * 16 + r_l;
            #pragma unroll
            for (int nt = 0; nt < 10; nt++) {
                int col = warp_n * 80 + nt * 8 + c_l;
                *(float2*)(po + (size_t)row * NDIM + col) = make_float2(acc[nt][0], acc[nt][1]);
                *(float2*)(po + (size_t)(row + 8) * NDIM + col) = make_float2(acc[nt][2], acc[nt][3]);
            }
        }
        gbar(++bar_n);

        // ================= Phase 3: split-K reduce + squash ================
        {
            const int TOT = BATCH * NDIM;          // 40960
            #pragma unroll
            for (int base = 0; base < TOT; base += GRID * THREADS) {
                int idx = base + cta * THREADS + tid;
                if (idx < TOT) {
                    float a0 = 0.f, a1 = 0.f, a2 = 0.f, a3 = 0.f;
                    #pragma unroll
                    for (int sp = 0; sp < SPLITS_S; sp += 4) {
                        a0 += g_part_s[(size_t)(sp + 0) * TOT + idx];
                        a1 += g_part_s[(size_t)(sp + 1) * TOT + idx];
                        a2 += g_part_s[(size_t)(sp + 2) * TOT + idx];
                        a3 += g_part_s[(size_t)(sp + 3) * TOT + idx];
                    }
                    float s = (a0 + a1) + (a2 + a3);
                    float sq = s * s;
                    sq += __shfl_xor_sync(0xffffffffu, sq, 8);
                    sq += __shfl_xor_sync(0xffffffffu, sq, 4);
                    sq += __shfl_xor_sync(0xffffffffu, sq, 2);
                    sq += __shfl_xor_sync(0xffffffffu, sq, 1);
                    float scale = sq / ((1.0f + sq) * sqrtf(sq + 1e-9f));
                    float v = s * scale;
                    if (t == 2) {
                        out[idx] = v;
                    } else {
                        int b = idx / NDIM;
                        int ou = idx - b * NDIM;
                        __nv_bfloat16 h, l;
                        split_bf16(v, h, l);
                        g_vT_hi[(size_t)ou * BATCH + b] = h;
                        g_vT_lo[(size_t)ou * BATCH + b] = l;
                    }
                }
            }
        }
        if (t == 2) break;
        gbar(++bar_n);

        // ================= Phase 4: M-GEMM + fused b-update ================
        {
            int m0 = cta * 64;

            #pragma unroll
            for (int c = 0; c < 4; c++) {
                int kb = c * 64;
                #pragma unroll
                for (int r = 0; r < 2; r++) {
                    int e = tid + (r << 8);
                    int row = e >> 3, j = e & 7;
                    cp16(sb + swz(SG_AH + c * 8192, row, j),
                         g_inpT_hi + (size_t)(m0 + row) * BATCH + kb + j * 8);
                }
                #pragma unroll
                for (int r = 0; r < 5; r++) {
                    int e = tid + (r << 8);
                    int row = e >> 3, j = e & 7;
                    cp16(sb + swz(SG_BH + c * 20480, row, j),
                         g_vT_hi + (size_t)row * BATCH + kb + j * 8);
                }
                cp_commit();
            }
            #pragma unroll
            for (int c = 0; c < 4; c++) {
                #pragma unroll
                for (int r = 0; r < 5; r++) {
                    int e = tid + (r << 8);
                    int row = e >> 3, j = e & 7;
                    cp16(sb + swz(SG_BL + c * 20480, row, j),
                         g_vT_lo + (size_t)row * BATCH + c * 64 + j * 8);
                }
                cp_commit();
            }
            #pragma unroll
            for (int c = 0; c < 4; c++) {
                #pragma unroll
                for (int r = 0; r < 2; r++) {
                    int e = tid + (r << 8);
                    int row = e >> 3, j = e & 7;
                    cp16(sb + swz(SG_AL + c * 8192, row, j),
                         g_inpT_lo + (size_t)(m0 + row) * BATCH + c * 64 + j * 8);
                }
                cp_commit();
            }

            float acc[10][4];
            #pragma unroll
            for (int nt = 0; nt < 10; nt++)
                #pragma unroll
                for (int r = 0; r < 4; r++) acc[nt][r] = 0.f;

            auto do_chunk = [&](uint32_t aBase, uint32_t bBase) {
                #pragma unroll
                for (int ks = 0; ks < 4; ks++) {
                    uint32_t af[4], bf[10][2];
                    int arow = warp_m * 16 + a_row_l;
                    ldsm4(af[0], af[1], af[2], af[3],
                          sb + swz(aBase, arow, (ks << 1) | a_c16_l));
                    #pragma unroll
                    for (int p = 0; p < 5; p++) {
                        int brow = warp_n * 80 + p * 16 + b_dn_l;
                        ldsm4(bf[2*p][0], bf[2*p][1], bf[2*p+1][0], bf[2*p+1][1],
                              sb + swz(bBase, brow, (ks << 1) | b_c16_l));
                    }
                    #pragma unroll
                    for (int nt = 0; nt < 10; nt++)
                        mma16816(acc[nt], af, bf[nt]);
                }
            };

            cp_wait<8>();
            __syncthreads();
            #pragma unroll
            for (int c = 0; c < 4; c++)
                do_chunk(SG_AH + c * 8192, SG_BH + c * 20480);
            cp_wait<4>();
            __syncthreads();
            #pragma unroll
            for (int c = 0; c < 4; c++)
                do_chunk(SG_AH + c * 8192, SG_BL + c * 20480);
            cp_wait<0>();
            __syncthreads();
            #pragma unroll
            for (int c = 0; c < 4; c++)
                do_chunk(SG_AL + c * 8192, SG_BH + c * 20480);

            // Stage M tile [64][160] fp32 in smem (reuses staging space).
            __syncthreads();
            float* M_s = (float*)sm;
            int r_l = lane >> 2, c_l = (lane & 3) * 2;
            int row = warp_m * 16 + r_l;
            #pragma unroll
            for (int nt = 0; nt < 10; nt++) {
                int col = warp_n * 80 + nt * 8 + c_l;
                *(float2*)(M_s + row * NDIM + col) = make_float2(acc[nt][0], acc[nt][1]);
                *(float2*)(M_s + (row + 8) * NDIM + col) = make_float2(acc[nt][2], acc[nt][3]);
            }
            __syncthreads();

            // delta[i,o] = (1/B) sum_{k,u} W[i,o,u,k]*M[i8+k][o16+u]
            #pragma unroll
            for (int ee = 0; ee < 10; ee++) {
                int e = wid * 10 + ee;
                int i_rel = e / 10, o = e - i_rel * 10;
                int i = cta * 8 + i_rel;
                float sum = 0.f;
                #pragma unroll
                for (int j = 0; j < 4; j++) {
                    int f = lane + (j << 5);
                    int k = f >> 4, u = f & 15;
                    sum = fmaf(W[(size_t)i * 1280 + (o << 7) + (u << 3) + k],
                               M_s[(i_rel * 8 + k) * NDIM + o * 16 + u], sum);
                }
                #pragma unroll
                for (int off = 16; off; off >>= 1)
                    sum += __shfl_xor_sync(0xffffffffu, sum, off);
                if (lane == 0) {
                    float d = sum * (1.0f / (float)BATCH);
                    int gw = i * OUTCH + o;
                    g_b[gw] = (t == 0) ? d : (g_b[gw] + d);
                }
            }
        }
        gbar(++bar_n);
    }
}

// ---------------------------------------------------------------------------
extern "C" void kernel_launch(void* const* d_in, const int* in_sizes, int n_in,
                              void* d_out, int out_size) {
    const float* inp = (const float*)d_in[0];  // [256,1152,8]
    const float* W   = (const float*)d_in[1];  // [1152,10,16,8]
    float* out = (float*)d_out;                // [256,10,16]

    cudaFuncSetAttribute(fused, cudaFuncAttributeMaxDynamicSharedMemorySize, SG_TOT);

    conv_inp<<<dim3(KDIM / 32, BATCH / 32), dim3(32, 8)>>>(inp);
    fused<<<GRID, THREADS, SG_TOT>>>(W, out);
}

// round 10
// speedup vs baseline: 1.1302x; 1.1302x over previous
#include <cuda_runtime.h>
#include <cuda_bf16.h>
#include <cstdint>

// CapsNet dynamic routing. u_hat never materialized; bf16 hi/lo 3-pass GEMMs
// on mma.sync (m16n8k16, fp32 accum). Multi-kernel (graph-replayed), one-shot
// cp.async staging with progressive wait_group overlap.
//   inp: [256,1152,8] fp32, W: [1152,10,16,8] fp32, out v: [256,10,16] fp32
//
// All __device__ globals referenced only inside device code (host-passed
// __device__ symbols silently resolve to ATS host memory on GB300).

#define BATCH   256
#define INCH    1152
#define INU     8
#define OUTCH   10
#define OUTU    16
#define KDIM    (INCH*INU)     // 9216
#define NDIM    (OUTCH*OUTU)   // 160
#define NCHUNK  144            // 64-k chunks (8 capsules each)
#define SPLITS_S 36            // s-GEMM K splits (4 chunks = 256 K per CTA)

// ---------------- device globals ----------------
__device__ __nv_bfloat16 g_inp_hi[BATCH * KDIM];
__device__ __nv_bfloat16 g_inp_lo[BATCH * KDIM];
__device__ __nv_bfloat16 g_inpT_hi[KDIM * BATCH];
__device__ __nv_bfloat16 g_inpT_lo[KDIM * BATCH];
__device__ __nv_bfloat16 g_vT_hi[NDIM * BATCH];
__device__ __nv_bfloat16 g_vT_lo[NDIM * BATCH];
__device__ __nv_bfloat16 g_Bt_hi[NCHUNK * NDIM * 64];  // chunk-tiled Wc
__device__ __nv_bfloat16 g_Bt_lo[NCHUNK * NDIM * 64];
__device__ float g_part_s[SPLITS_S * BATCH * NDIM];    // 5.9 MB
__device__ float g_b[INCH * OUTCH];

__device__ __forceinline__ uint32_t smem_to_u32(const void* p) {
    uint32_t a;
    asm("{ .reg .u64 t; cvta.to.shared.u64 t, %1; cvt.u32.u64 %0, t; }"
        : "=r"(a) : "l"(p));
    return a;
}
__device__ __forceinline__ void split_bf16(float x, __nv_bfloat16& h, __nv_bfloat16& l) {
    h = __float2bfloat16(x);
    l = __float2bfloat16(x - __bfloat162float(h));
}
__device__ __forceinline__ void ldsm4(uint32_t& r0, uint32_t& r1, uint32_t& r2,
                                      uint32_t& r3, uint32_t addr) {
    asm volatile("ldmatrix.sync.aligned.m8n8.x4.shared.b16 {%0,%1,%2,%3}, [%4];"
                 : "=r"(r0), "=r"(r1), "=r"(r2), "=r"(r3) : "r"(addr));
}
__device__ __forceinline__ void mma16816(float* d, const uint32_t* a,
                                         const uint32_t* b) {
    asm volatile(
        "mma.sync.aligned.m16n8k16.row.col.f32.bf16.bf16.f32 "
        "{%0,%1,%2,%3}, {%4,%5,%6,%7}, {%8,%9}, {%0,%1,%2,%3};"
        : "+f"(d[0]), "+f"(d[1]), "+f"(d[2]), "+f"(d[3])
        : "r"(a[0]), "r"(a[1]), "r"(a[2]), "r"(a[3]), "r"(b[0]), "r"(b[1]));
}
__device__ __forceinline__ void cp16(uint32_t dst, const void* src) {
    asm volatile("cp.async.cg.shared.global [%0], [%1], 16;"
                 :: "r"(dst), "l"(src));
}
__device__ __forceinline__ void cp_commit() {
    asm volatile("cp.async.commit_group;");
}
template <int N>
__device__ __forceinline__ void cp_wait() {
    asm volatile("cp.async.wait_group %0;" :: "n"(N));
}

// ---------------------------------------------------------------------------
// One-time: inp fp32 -> bf16 hi/lo, plus transposed copies.
// ---------------------------------------------------------------------------
__global__ void conv_inp(const float* __restrict__ inp) {
    __shared__ __nv_bfloat16 sh_hi[32][33];
    __shared__ __nv_bfloat16 sh_lo[32][33];
    int ik0 = blockIdx.x * 32, b0 = blockIdx.y * 32;
    int tx = threadIdx.x, ty = threadIdx.y;
    #pragma unroll
    for (int j = 0; j < 4; j++) {
        int bl = ty + 8 * j;
        float x = inp[(size_t)(b0 + bl) * KDIM + ik0 + tx];
        __nv_bfloat16 h, l;
        split_bf16(x, h, l);
        g_inp_hi[(size_t)(b0 + bl) * KDIM + ik0 + tx] = h;
        g_inp_lo[(size_t)(b0 + bl) * KDIM + ik0 + tx] = l;
        sh_hi[tx][bl] = h;
        sh_lo[tx][bl] = l;
    }
    __syncthreads();
    #pragma unroll
    for (int j = 0; j < 4; j++) {
        int ikl = ty + 8 * j;
        g_inpT_hi[(size_t)(ik0 + ikl) * BATCH + b0 + tx] = sh_hi[ikl][tx];
        g_inpT_lo[(size_t)(ik0 + ikl) * BATCH + b0 + tx] = sh_lo[ikl][tx];
    }
}

// ---------------------------------------------------------------------------
// Wc build, chunk-tiled: g_Bt[chunk][ou][64] = c[i,o]*W[i,o,u,k] (bf16 hi/lo).
// ---------------------------------------------------------------------------
__global__ void wc_tiled(const float* __restrict__ W, int t) {
    __shared__ float c_s[8][10];
    int chunk = blockIdx.x, i0 = chunk * 8;
    int tid = threadIdx.x;
    if (tid < 8) {
        int i = i0 + tid;
        if (t == 0) {
            #pragma unroll
            for (int o = 0; o < OUTCH; o++) c_s[tid][o] = 0.1f;
        } else {
            float bv[OUTCH], m = -1e30f;
            #pragma unroll
            for (int o = 0; o < OUTCH; o++) {
                bv[o] = g_b[i * OUTCH + o];
                m = fmaxf(m, bv[o]);
            }
            float sum = 0.f;
            #pragma unroll
            for (int o = 0; o < OUTCH; o++) { bv[o] = expf(bv[o] - m); sum += bv[o]; }
            float inv = 1.0f / sum;
            #pragma unroll
            for (int o = 0; o < OUTCH; o++) c_s[tid][o] = bv[o] * inv;
        }
    }
    __syncthreads();
    const float4* W4 = (const float4*)(W + (size_t)i0 * 1280);
    __nv_bfloat16* bh = g_Bt_hi + (size_t)chunk * (NDIM * 64);
    __nv_bfloat16* bl = g_Bt_lo + (size_t)chunk * (NDIM * 64);
    #pragma unroll
    for (int r = 0; r < 10; r++) {
        int q = tid + (r << 8);              // 0..2559 float4s (8 caps x 320)
        int i_off = q / 320;
        int rem = q - i_off * 320;
        int o = rem >> 5;
        int rem2 = rem & 31;
        int u = rem2 >> 1, kh = rem2 & 1;
        float4 f = W4[q];
        float cv = c_s[i_off][o];
        __nv_bfloat16 h0,l0,h1,l1,h2,l2,h3,l3;
        split_bf16(f.x * cv, h0, l0);
        split_bf16(f.y * cv, h1, l1);
        split_bf16(f.z * cv, h2, l2);
        split_bf16(f.w * cv, h3, l3);
        uint2 ph, pl;
        ph.x = (uint32_t)__bfloat16_as_ushort(h0) | ((uint32_t)__bfloat16_as_ushort(h1) << 16);
        ph.y = (uint32_t)__bfloat16_as_ushort(h2) | ((uint32_t)__bfloat16_as_ushort(h3) << 16);
        pl.x = (uint32_t)__bfloat16_as_ushort(l0) | ((uint32_t)__bfloat16_as_ushort(l1) << 16);
        pl.y = (uint32_t)__bfloat16_as_ushort(l2) | ((uint32_t)__bfloat16_as_ushort(l3) << 16);
        int off = (o * 16 + u) * 64 + i_off * 8 + kh * 4;
        *(uint2*)(bh + off) = ph;
        *(uint2*)(bl + off) = pl;
    }
}

// ---------------------------------------------------------------------------
// One-shot staging layout (224 KB), shared by both GEMMs:
//   AH: 4 chunks x 64 rows x 128 B  = 32 KB   at 0
//   AL: 32 KB                                 at 32768
//   BH: 4 chunks x 160 rows x 128 B = 80 KB   at 65536
//   BL: 80 KB                                 at 147456
// Swizzle: col16 ^= row&7 (applied at cp.async write and ldmatrix read).
// Commit groups: 0..3 = (Ah+Bh)_c, 4..7 = Bl_c, 8..11 = Al_c.
// Progressive waits: one group retired per chunk-pass.
// ---------------------------------------------------------------------------
#define SG_AH 0
#define SG_AL 32768
#define SG_BH 65536
#define SG_BL 147456
#define SG_TOT 229376

__device__ __forceinline__ uint32_t swz(uint32_t base, int row, int col16) {
    return base + (uint32_t)row * 128 + (uint32_t)((col16 ^ (row & 7)) << 4);
}

// Shared mainloop body (both GEMMs): issues nothing, computes one 64-K chunk.
#define DO_CHUNK(aBase, bBase)                                                \
    do {                                                                      \
        _Pragma("unroll")                                                     \
        for (int ks = 0; ks < 4; ks++) {                                      \
            uint32_t af[4], bf[10][2];                                        \
            int arow = warp_m * 16 + a_row_l;                                 \
            ldsm4(af[0], af[1], af[2], af[3],                                 \
                  sb + swz((aBase), arow, (ks << 1) | a_c16_l));              \
            _Pragma("unroll")                                                 \
            for (int p = 0; p < 5; p++) {                                     \
                int brow = warp_n * 80 + p * 16 + b_dn_l;                     \
                ldsm4(bf[2*p][0], bf[2*p][1], bf[2*p+1][0], bf[2*p+1][1],     \
                      sb + swz((bBase), brow, (ks << 1) | b_c16_l));          \
            }                                                                 \
            _Pragma("unroll")                                                 \
            for (int nt = 0; nt < 10; nt++)                                   \
                mma16816(acc[nt], af, bf[nt]);                                \
        }                                                                     \
    } while (0)

#define PROGRESSIVE_MAINLOOP()                                                \
    cp_wait<11>(); __syncthreads(); DO_CHUNK(SG_AH + 0*8192, SG_BH + 0*20480);\
    cp_wait<10>(); __syncthreads(); DO_CHUNK(SG_AH + 1*8192, SG_BH + 1*20480);\
    cp_wait<9>();  __syncthreads(); DO_CHUNK(SG_AH + 2*8192, SG_BH + 2*20480);\
    cp_wait<8>();  __syncthreads(); DO_CHUNK(SG_AH + 3*8192, SG_BH + 3*20480);\
    cp_wait<7>();  __syncthreads(); DO_CHUNK(SG_AH + 0*8192, SG_BL + 0*20480);\
    cp_wait<6>();  __syncthreads(); DO_CHUNK(SG_AH + 1*8192, SG_BL + 1*20480);\
    cp_wait<5>();  __syncthreads(); DO_CHUNK(SG_AH + 2*8192, SG_BL + 2*20480);\
    cp_wait<4>();  __syncthreads(); DO_CHUNK(SG_AH + 3*8192, SG_BL + 3*20480);\
    cp_wait<3>();  __syncthreads(); DO_CHUNK(SG_AL + 0*8192, SG_BH + 0*20480);\
    cp_wait<2>();  __syncthreads(); DO_CHUNK(SG_AL + 1*8192, SG_BH + 1*20480);\
    cp_wait<1>();  __syncthreads(); DO_CHUNK(SG_AL + 2*8192, SG_BH + 2*20480);\
    cp_wait<0>();  __syncthreads(); DO_CHUNK(SG_AL + 3*8192, SG_BH + 3*20480);

// ---------------------------------------------------------------------------
// s-GEMM: grid (4 Mtiles, 36 Ksplits) = 144 CTAs, 256 thr, 8 warps (4M x 2N).
// ---------------------------------------------------------------------------
__global__ void __launch_bounds__(256, 1)
gemm_s(int t_unused) {
    extern __shared__ char sm[];
    uint32_t sb = smem_to_u32(sm);
    int tid = threadIdx.x, lane = tid & 31, wid = tid >> 5;
    int warp_m = wid & 3, warp_n = wid >> 2;
    int m0 = blockIdx.x * 64;
    int chunk0 = blockIdx.y * 4;

    #pragma unroll
    for (int c = 0; c < 4; c++) {
        int kb = (chunk0 + c) * 64;
        #pragma unroll
        for (int r = 0; r < 2; r++) {
            int e = tid + (r << 8);
            int row = e >> 3, j = e & 7;
            cp16(sb + swz(SG_AH + c * 8192, row, j),
                 g_inp_hi + (size_t)(m0 + row) * KDIM + kb + j * 8);
        }
        #pragma unroll
        for (int r = 0; r < 5; r++) {
            int e = tid + (r << 8);
            int row = e >> 3, j = e & 7;
            cp16(sb + swz(SG_BH + c * 20480, row, j),
                 g_Bt_hi + (size_t)(chunk0 + c) * (NDIM * 64) + e * 8);
        }
        cp_commit();
    }
    #pragma unroll
    for (int c = 0; c < 4; c++) {
        #pragma unroll
        for (int r = 0; r < 5; r++) {
            int e = tid + (r << 8);
            int row = e >> 3, j = e & 7;
            cp16(sb + swz(SG_BL + c * 20480, row, j),
                 g_Bt_lo + (size_t)(chunk0 + c) * (NDIM * 64) + e * 8);
        }
        cp_commit();
    }
    #pragma unroll
    for (int c = 0; c < 4; c++) {
        int kb = (chunk0 + c) * 64;
        #pragma unroll
        for (int r = 0; r < 2; r++) {
            int e = tid + (r << 8);
            int row = e >> 3, j = e & 7;
            cp16(sb + swz(SG_AL + c * 8192, row, j),
                 g_inp_lo + (size_t)(m0 + row) * KDIM + kb + j * 8);
        }
        cp_commit();
    }

    float acc[10][4];
    #pragma unroll
    for (int nt = 0; nt < 10; nt++)
        #pragma unroll
        for (int r = 0; r < 4; r++) acc[nt][r] = 0.f;

    int a_row_l = ((lane >> 3) & 1) * 8 + (lane & 7);
    int a_c16_l = lane >> 4;
    int b_dn_l  = ((lane >> 4) & 1) * 8 + (lane & 7);
    int b_c16_l = (lane >> 3) & 1;

    PROGRESSIVE_MAINLOOP();

    float* out = g_part_s + (size_t)blockIdx.y * (BATCH * NDIM);
    int r_l = lane >> 2, c_l = (lane & 3) * 2;
    int row = m0 + warp_m * 16 + r_l;
    #pragma unroll
    for (int nt = 0; nt < 10; nt++) {
        int col = warp_n * 80 + nt * 8 + c_l;
        *(float2*)(out + (size_t)row * NDIM + col) = make_float2(acc[nt][0], acc[nt][1]);
        *(float2*)(out + (size_t)(row + 8) * NDIM + col) = make_float2(acc[nt][2], acc[nt][3]);
    }
}

// ---------------------------------------------------------------------------
// Split-K reduce + squash, float2 per thread. 160 blocks x 128 threads =
// 20480 threads x 2 elems. (b,o) group = 8 consecutive threads -> xor 4/2/1.
// ---------------------------------------------------------------------------
__global__ void squash_k(float* __restrict__ out, int t) {
    int idx2 = blockIdx.x * 128 + threadIdx.x;     // float2 index
    const float2* P = (const float2*)g_part_s;
    const int TOT2 = BATCH * NDIM / 2;             // 20480
    float2 a0 = make_float2(0.f, 0.f), a1 = a0, a2 = a0, a3 = a0;
    #pragma unroll
    for (int sp = 0; sp < SPLITS_S; sp += 4) {
        float2 v0 = P[(size_t)(sp + 0) * TOT2 + idx2];
        float2 v1 = P[(size_t)(sp + 1) * TOT2 + idx2];
        float2 v2 = P[(size_t)(sp + 2) * TOT2 + idx2];
        float2 v3 = P[(size_t)(sp + 3) * TOT2 + idx2];
        a0.x += v0.x; a0.y += v0.y;
        a1.x += v1.x; a1.y += v1.y;
        a2.x += v2.x; a2.y += v2.y;
        a3.x += v3.x; a3.y += v3.y;
    }
    float sx = (a0.x + a1.x) + (a2.x + a3.x);
    float sy = (a0.y + a1.y) + (a2.y + a3.y);
    float sq = sx * sx + sy * sy;
    sq += __shfl_xor_sync(0xffffffffu, sq, 4);
    sq += __shfl_xor_sync(0xffffffffu, sq, 2);
    sq += __shfl_xor_sync(0xffffffffu, sq, 1);
    float scale = sq / ((1.0f + sq) * sqrtf(sq + 1e-9f));
    float vx = sx * scale, vy = sy * scale;
    int idx = idx2 * 2;
    if (t == 2) {
        *(float2*)(out + idx) = make_float2(vx, vy);
    } else {
        int b = idx / NDIM;
        int ou = idx - b * NDIM;                   // even; ou+1 same b
        __nv_bfloat16 hx, lx, hy, ly;
        split_bf16(vx, hx, lx);
        split_bf16(vy, hy, ly);
        g_vT_hi[(size_t)ou * BATCH + b] = hx;
        g_vT_lo[(size_t)ou * BATCH + b] = lx;
        g_vT_hi[(size_t)(ou + 1) * BATCH + b] = hy;
        g_vT_lo[(size_t)(ou + 1) * BATCH + b] = ly;
    }
}

// ---------------------------------------------------------------------------
// M-GEMM (M[ik,ou] = inpT @ vT^T) with fused b-update. grid 144, one-shot
// staging + progressive waits (same layout as gemm_s).
// ---------------------------------------------------------------------------
__global__ void __launch_bounds__(256, 1)
gemm_m(const float* __restrict__ W, int t) {
    extern __shared__ char sm[];
    uint32_t sb = smem_to_u32(sm);
    int tid = threadIdx.x, lane = tid & 31, wid = tid >> 5;
    int warp_m = wid & 3, warp_n = wid >> 2;
    int m0 = blockIdx.x * 64;

    #pragma unroll
    for (int c = 0; c < 4; c++) {
        int kb = c * 64;
        #pragma unroll
        for (int r = 0; r < 2; r++) {
            int e = tid + (r << 8);
            int row = e >> 3, j = e & 7;
            cp16(sb + swz(SG_AH + c * 8192, row, j),
                 g_inpT_hi + (size_t)(m0 + row) * BATCH + kb + j * 8);
        }
        #pragma unroll
        for (int r = 0; r < 5; r++) {
            int e = tid + (r << 8);
            int row = e >> 3, j = e & 7;
            cp16(sb + swz(SG_BH + c * 20480, row, j),
                 g_vT_hi + (size_t)row * BATCH + kb + j * 8);
        }
        cp_commit();
    }
    #pragma unroll
    for (int c = 0; c < 4; c++) {
        #pragma unroll
        for (int r = 0; r < 5; r++) {
            int e = tid + (r << 8);
            int row = e >> 3, j = e & 7;
            cp16(sb + swz(SG_BL + c * 20480, row, j),
                 g_vT_lo + (size_t)row * BATCH + c * 64 + j * 8);
        }
        cp_commit();
    }
    #pragma unroll
    for (int c = 0; c < 4; c++) {
        #pragma unroll
        for (int r = 0; r < 2; r++) {
            int e = tid + (r << 8);
            int row = e >> 3, j = e & 7;
            cp16(sb + swz(SG_AL + c * 8192, row, j),
                 g_inpT_lo + (size_t)(m0 + row) * BATCH + c * 64 + j * 8);
        }
        cp_commit();
    }

    float acc[10][4];
    #pragma unroll
    for (int nt = 0; nt < 10; nt++)
        #pragma unroll
        for (int r = 0; r < 4; r++) acc[nt][r] = 0.f;

    int a_row_l = ((lane >> 3) & 1) * 8 + (lane & 7);
    int a_c16_l = lane >> 4;
    int b_dn_l  = ((lane >> 4) & 1) * 8 + (lane & 7);
    int b_c16_l = (lane >> 3) & 1;

    PROGRESSIVE_MAINLOOP();

    // Stage M tile [64][160] fp32 in smem (reuses staging space).
    __syncthreads();
    float* M_s = (float*)sm;
    int r_l = lane >> 2, c_l = (lane & 3) * 2;
    int row = warp_m * 16 + r_l;
    #pragma unroll
    for (int nt = 0; nt < 10; nt++) {
        int col = warp_n * 80 + nt * 8 + c_l;
        *(float2*)(M_s + row * NDIM + col) = make_float2(acc[nt][0], acc[nt][1]);
        *(float2*)(M_s + (row + 8) * NDIM + col) = make_float2(acc[nt][2], acc[nt][3]);
    }
    __syncthreads();

    // delta[i,o] = (1/B) sum_{k,u} W[i,o,u,k]*M[i8+k][o16+u]
    #pragma unroll
    for (int ee = 0; ee < 10; ee++) {
        int e = wid * 10 + ee;
        int i_rel = e / 10, o = e - i_rel * 10;
        int i = blockIdx.x * 8 + i_rel;
        float sum = 0.f;
        #pragma unroll
        for (int j = 0; j < 4; j++) {
            int f = lane + (j << 5);
            int k = f >> 4, u = f & 15;
            sum = fmaf(W[(size_t)i * 1280 + (o << 7) + (u << 3) + k],
                       M_s[(i_rel * 8 + k) * NDIM + o * 16 + u], sum);
        }
        #pragma unroll
        for (int off = 16; off; off >>= 1)
            sum += __shfl_xor_sync(0xffffffffu, sum, off);
        if (lane == 0) {
            float d = sum * (1.0f / (float)BATCH);
            int gw = i * OUTCH + o;
            g_b[gw] = (t == 0) ? d : (g_b[gw] + d);
        }
    }
}

// ---------------------------------------------------------------------------
extern "C" void kernel_launch(void* const* d_in, const int* in_sizes, int n_in,
                              void* d_out, int out_size) {
    const float* inp = (const float*)d_in[0];  // [256,1152,8]
    const float* W   = (const float*)d_in[1];  // [1152,10,16,8]
    float* out = (float*)d_out;                // [256,10,16]

    cudaFuncSetAttribute(gemm_s, cudaFuncAttributeMaxDynamicSharedMemorySize, SG_TOT);
    cudaFuncSetAttribute(gemm_m, cudaFuncAttributeMaxDynamicSharedMemorySize, SG_TOT);

    conv_inp<<<dim3(KDIM / 32, BATCH / 32), dim3(32, 8)>>>(inp);

    for (int t = 0; t < 3; t++) {
        wc_tiled<<<NCHUNK, 256>>>(W, t);
        gemm_s<<<dim3(4, SPLITS_S), 256, SG_TOT>>>(0);
        squash_k<<<BATCH * NDIM / 256, 128>>>(out, t);
        if (t < 2)
            gemm_m<<<KDIM / 64, 256, SG_TOT>>>(W, t);
    }
}

// round 11
// speedup vs baseline: 1.1347x; 1.0040x over previous
#include <cuda_runtime.h>
#include <cuda_bf16.h>
#include <cstdint>

// CapsNet dynamic routing. u_hat never materialized; bf16 hi/lo 3-pass GEMMs
// on mma.sync (m16n8k16, fp32 accum). One-shot cp.async staging with
// progressive wait_group overlap. Wc-build for t+1 fused into gemm_m(t).
//   inp: [256,1152,8] fp32, W: [1152,10,16,8] fp32, out v: [256,10,16] fp32
//
// All __device__ globals referenced only inside device code (host-passed
// __device__ symbols silently resolve to ATS host memory on GB300).

#define BATCH   256
#define INCH    1152
#define INU     8
#define OUTCH   10
#define OUTU    16
#define KDIM    (INCH*INU)     // 9216
#define NDIM    (OUTCH*OUTU)   // 160
#define NCHUNK  144            // 64-k chunks (8 capsules each)
#define SPLITS_S 36            // s-GEMM K splits (4 chunks = 256 K per CTA)

// ---------------- device globals ----------------
__device__ __nv_bfloat16 g_inp_hi[BATCH * KDIM];
__device__ __nv_bfloat16 g_inp_lo[BATCH * KDIM];
__device__ __nv_bfloat16 g_inpT_hi[KDIM * BATCH];
__device__ __nv_bfloat16 g_inpT_lo[KDIM * BATCH];
__device__ __nv_bfloat16 g_vT_hi[NDIM * BATCH];
__device__ __nv_bfloat16 g_vT_lo[NDIM * BATCH];
__device__ __nv_bfloat16 g_Bt_hi[NCHUNK * NDIM * 64];  // chunk-tiled Wc
__device__ __nv_bfloat16 g_Bt_lo[NCHUNK * NDIM * 64];
__device__ float g_part_s[SPLITS_S * BATCH * NDIM];    // 5.9 MB
__device__ float g_b[INCH * OUTCH];

__device__ __forceinline__ uint32_t smem_to_u32(const void* p) {
    uint32_t a;
    asm("{ .reg .u64 t; cvta.to.shared.u64 t, %1; cvt.u32.u64 %0, t; }"
        : "=r"(a) : "l"(p));
    return a;
}
__device__ __forceinline__ void split_bf16(float x, __nv_bfloat16& h, __nv_bfloat16& l) {
    h = __float2bfloat16(x);
    l = __float2bfloat16(x - __bfloat162float(h));
}
__device__ __forceinline__ void ldsm4(uint32_t& r0, uint32_t& r1, uint32_t& r2,
                                      uint32_t& r3, uint32_t addr) {
    asm volatile("ldmatrix.sync.aligned.m8n8.x4.shared.b16 {%0,%1,%2,%3}, [%4];"
                 : "=r"(r0), "=r"(r1), "=r"(r2), "=r"(r3) : "r"(addr));
}
__device__ __forceinline__ void mma16816(float* d, const uint32_t* a,
                                         const uint32_t* b) {
    asm volatile(
        "mma.sync.aligned.m16n8k16.row.col.f32.bf16.bf16.f32 "
        "{%0,%1,%2,%3}, {%4,%5,%6,%7}, {%8,%9}, {%0,%1,%2,%3};"
        : "+f"(d[0]), "+f"(d[1]), "+f"(d[2]), "+f"(d[3])
        : "r"(a[0]), "r"(a[1]), "r"(a[2]), "r"(a[3]), "r"(b[0]), "r"(b[1]));
}
__device__ __forceinline__ void cp16(uint32_t dst, const void* src) {
    asm volatile("cp.async.cg.shared.global [%0], [%1], 16;"
                 :: "r"(dst), "l"(src));
}
__device__ __forceinline__ void cp_commit() {
    asm volatile("cp.async.commit_group;");
}
template <int N>
__device__ __forceinline__ void cp_wait() {
    asm volatile("cp.async.wait_group %0;" :: "n"(N));
}

// ---------------------------------------------------------------------------
// One-time: inp fp32 -> bf16 hi/lo, plus transposed copies.
// ---------------------------------------------------------------------------
__global__ void conv_inp(const float* __restrict__ inp) {
    __shared__ __nv_bfloat16 sh_hi[32][33];
    __shared__ __nv_bfloat16 sh_lo[32][33];
    int ik0 = blockIdx.x * 32, b0 = blockIdx.y * 32;
    int tx = threadIdx.x, ty = threadIdx.y;
    #pragma unroll
    for (int j = 0; j < 4; j++) {
        int bl = ty + 8 * j;
        float x = inp[(size_t)(b0 + bl) * KDIM + ik0 + tx];
        __nv_bfloat16 h, l;
        split_bf16(x, h, l);
        g_inp_hi[(size_t)(b0 + bl) * KDIM + ik0 + tx] = h;
        g_inp_lo[(size_t)(b0 + bl) * KDIM + ik0 + tx] = l;
        sh_hi[tx][bl] = h;
        sh_lo[tx][bl] = l;
    }
    __syncthreads();
    #pragma unroll
    for (int j = 0; j < 4; j++) {
        int ikl = ty + 8 * j;
        g_inpT_hi[(size_t)(ik0 + ikl) * BATCH + b0 + tx] = sh_hi[ikl][tx];
        g_inpT_lo[(size_t)(ik0 + ikl) * BATCH + b0 + tx] = sh_lo[ikl][tx];
    }
}

// ---------------------------------------------------------------------------
// Wc body (shared by wc_tiled kernel and gemm_m epilogue):
// g_Bt[chunk][ou][64] = c_s[i_off][o] * W[i,o,u,k] as bf16 hi/lo.
// ---------------------------------------------------------------------------
__device__ __forceinline__ void wc_body(const float* __restrict__ W, int chunk,
                                        const float (*c_s)[10], int tid) {
    const float4* W4 = (const float4*)(W + (size_t)chunk * 8 * 1280);
    __nv_bfloat16* bh = g_Bt_hi + (size_t)chunk * (NDIM * 64);
    __nv_bfloat16* bl = g_Bt_lo + (size_t)chunk * (NDIM * 64);
    #pragma unroll
    for (int r = 0; r < 10; r++) {
        int q = tid + (r << 8);              // 0..2559 float4s (8 caps x 320)
        int i_off = q / 320;
        int rem = q - i_off * 320;
        int o = rem >> 5;
        int rem2 = rem & 31;
        int u = rem2 >> 1, kh = rem2 & 1;
        float4 f = W4[q];
        float cv = c_s[i_off][o];
        __nv_bfloat16 h0,l0,h1,l1,h2,l2,h3,l3;
        split_bf16(f.x * cv, h0, l0);
        split_bf16(f.y * cv, h1, l1);
        split_bf16(f.z * cv, h2, l2);
        split_bf16(f.w * cv, h3, l3);
        uint2 ph, pl;
        ph.x = (uint32_t)__bfloat16_as_ushort(h0) | ((uint32_t)__bfloat16_as_ushort(h1) << 16);
        ph.y = (uint32_t)__bfloat16_as_ushort(h2) | ((uint32_t)__bfloat16_as_ushort(h3) << 16);
        pl.x = (uint32_t)__bfloat16_as_ushort(l0) | ((uint32_t)__bfloat16_as_ushort(l1) << 16);
        pl.y = (uint32_t)__bfloat16_as_ushort(l2) | ((uint32_t)__bfloat16_as_ushort(l3) << 16);
        int off = (o * 16 + u) * 64 + i_off * 8 + kh * 4;
        *(uint2*)(bh + off) = ph;
        *(uint2*)(bl + off) = pl;
    }
}

// Standalone Wc build, t=0 only (c = 0.1 constant).
__global__ void wc_tiled0(const float* __restrict__ W) {
    __shared__ float c_s[8][10];
    int tid = threadIdx.x;
    if (tid < 80) c_s[tid / 10][tid % 10] = 0.1f;
    __syncthreads();
    wc_body(W, blockIdx.x, c_s, tid);
}

// ---------------------------------------------------------------------------
// One-shot staging layout (224 KB), shared by both GEMMs:
//   AH: 4 chunks x 64 rows x 128 B  = 32 KB   at 0
//   AL: 32 KB                                 at 32768
//   BH: 4 chunks x 160 rows x 128 B = 80 KB   at 65536
//   BL: 80 KB                                 at 147456
// Swizzle: col16 ^= row&7. Commit groups: 0..3 = (Ah+Bh)_c, 4..7 = Bl_c,
// 8..11 = Al_c. Progressive waits: one group retired per chunk-pass.
// ---------------------------------------------------------------------------
#define SG_AH 0
#define SG_AL 32768
#define SG_BH 65536
#define SG_BL 147456
#define SG_TOT 229376

__device__ __forceinline__ uint32_t swz(uint32_t base, int row, int col16) {
    return base + (uint32_t)row * 128 + (uint32_t)((col16 ^ (row & 7)) << 4);
}

#define DO_CHUNK(aBase, bBase)                                                \
    do {                                                                      \
        _Pragma("unroll")                                                     \
        for (int ks = 0; ks < 4; ks++) {                                      \
            uint32_t af[4], bf[10][2];                                        \
            int arow = warp_m * 16 + a_row_l;                                 \
            ldsm4(af[0], af[1], af[2], af[3],                                 \
                  sb + swz((aBase), arow, (ks << 1) | a_c16_l));              \
            _Pragma("unroll")                                                 \
            for (int p = 0; p < 5; p++) {                                     \
                int brow = warp_n * 80 + p * 16 + b_dn_l;                     \
                ldsm4(bf[2*p][0], bf[2*p][1], bf[2*p+1][0], bf[2*p+1][1],     \
                      sb + swz((bBase), brow, (ks << 1) | b_c16_l));          \
            }                                                                 \
            _Pragma("unroll")                                                 \
            for (int nt = 0; nt < 10; nt++)                                   \
                mma16816(acc[nt], af, bf[nt]);                                \
        }                                                                     \
    } while (0)

#define PROGRESSIVE_MAINLOOP()                                                \
    cp_wait<11>(); __syncthreads(); DO_CHUNK(SG_AH + 0*8192, SG_BH + 0*20480);\
    cp_wait<10>(); __syncthreads(); DO_CHUNK(SG_AH + 1*8192, SG_BH + 1*20480);\
    cp_wait<9>();  __syncthreads(); DO_CHUNK(SG_AH + 2*8192, SG_BH + 2*20480);\
    cp_wait<8>();  __syncthreads(); DO_CHUNK(SG_AH + 3*8192, SG_BH + 3*20480);\
    cp_wait<7>();  __syncthreads(); DO_CHUNK(SG_AH + 0*8192, SG_BL + 0*20480);\
    cp_wait<6>();  __syncthreads(); DO_CHUNK(SG_AH + 1*8192, SG_BL + 1*20480);\
    cp_wait<5>();  __syncthreads(); DO_CHUNK(SG_AH + 2*8192, SG_BL + 2*20480);\
    cp_wait<4>();  __syncthreads(); DO_CHUNK(SG_AH + 3*8192, SG_BL + 3*20480);\
    cp_wait<3>();  __syncthreads(); DO_CHUNK(SG_AL + 0*8192, SG_BH + 0*20480);\
    cp_wait<2>();  __syncthreads(); DO_CHUNK(SG_AL + 1*8192, SG_BH + 1*20480);\
    cp_wait<1>();  __syncthreads(); DO_CHUNK(SG_AL + 2*8192, SG_BH + 2*20480);\
    cp_wait<0>();  __syncthreads(); DO_CHUNK(SG_AL + 3*8192, SG_BH + 3*20480);

// ---------------------------------------------------------------------------
// s-GEMM: grid (4 Mtiles, 36 Ksplits) = 144 CTAs, 256 thr, 8 warps (4M x 2N).
// ---------------------------------------------------------------------------
__global__ void __launch_bounds__(256, 1)
gemm_s(int t_unused) {
    extern __shared__ char sm[];
    uint32_t sb = smem_to_u32(sm);
    int tid = threadIdx.x, lane = tid & 31, wid = tid >> 5;
    int warp_m = wid & 3, warp_n = wid >> 2;
    int m0 = blockIdx.x * 64;
    int chunk0 = blockIdx.y * 4;

    #pragma unroll
    for (int c = 0; c < 4; c++) {
        int kb = (chunk0 + c) * 64;
        #pragma unroll
        for (int r = 0; r < 2; r++) {
            int e = tid + (r << 8);
            int row = e >> 3, j = e & 7;
            cp16(sb + swz(SG_AH + c * 8192, row, j),
                 g_inp_hi + (size_t)(m0 + row) * KDIM + kb + j * 8);
        }
        #pragma unroll
        for (int r = 0; r < 5; r++) {
            int e = tid + (r << 8);
            int row = e >> 3, j = e & 7;
            cp16(sb + swz(SG_BH + c * 20480, row, j),
                 g_Bt_hi + (size_t)(chunk0 + c) * (NDIM * 64) + e * 8);
        }
        cp_commit();
    }
    #pragma unroll
    for (int c = 0; c < 4; c++) {
        #pragma unroll
        for (int r = 0; r < 5; r++) {
            int e = tid + (r << 8);
            int row = e >> 3, j = e & 7;
            cp16(sb + swz(SG_BL + c * 20480, row, j),
                 g_Bt_lo + (size_t)(chunk0 + c) * (NDIM * 64) + e * 8);
        }
        cp_commit();
    }
    #pragma unroll
    for (int c = 0; c < 4; c++) {
        int kb = (chunk0 + c) * 64;
        #pragma unroll
        for (int r = 0; r < 2; r++) {
            int e = tid + (r << 8);
            int row = e >> 3, j = e & 7;
            cp16(sb + swz(SG_AL + c * 8192, row, j),
                 g_inp_lo + (size_t)(m0 + row) * KDIM + kb + j * 8);
        }
        cp_commit();
    }

    float acc[10][4];
    #pragma unroll
    for (int nt = 0; nt < 10; nt++)
        #pragma unroll
        for (int r = 0; r < 4; r++) acc[nt][r] = 0.f;

    int a_row_l = ((lane >> 3) & 1) * 8 + (lane & 7);
    int a_c16_l = lane >> 4;
    int b_dn_l  = ((lane >> 4) & 1) * 8 + (lane & 7);
    int b_c16_l = (lane >> 3) & 1;

    PROGRESSIVE_MAINLOOP();

    float* out = g_part_s + (size_t)blockIdx.y * (BATCH * NDIM);
    int r_l = lane >> 2, c_l = (lane & 3) * 2;
    int row = m0 + warp_m * 16 + r_l;
    #pragma unroll
    for (int nt = 0; nt < 10; nt++) {
        int col = warp_n * 80 + nt * 8 + c_l;
        *(float2*)(out + (size_t)row * NDIM + col) = make_float2(acc[nt][0], acc[nt][1]);
        *(float2*)(out + (size_t)(row + 8) * NDIM + col) = make_float2(acc[nt][2], acc[nt][3]);
    }
}

// ---------------------------------------------------------------------------
// Split-K reduce + squash: 320 blocks x 256 thr = 64 float2-elems x 4 groups
// of 9 splits; smem combine, 8-thread shuffle norm.
// ---------------------------------------------------------------------------
__global__ void squash_k(float* __restrict__ out, int t) {
    __shared__ float2 red[4][64];
    int tid = threadIdx.x;
    int e2 = tid & 63;
    int grp = tid >> 6;                       // 0..3
    int idx2 = blockIdx.x * 64 + e2;          // float2 index
    const float2* P = (const float2*)g_part_s;
    const int TOT2 = BATCH * NDIM / 2;        // 20480

    float2 a0 = make_float2(0.f, 0.f), a1 = a0, a2 = a0;
    #pragma unroll
    for (int j = 0; j < 9; j += 3) {
        float2 v0 = P[(size_t)(grp * 9 + j + 0) * TOT2 + idx2];
        float2 v1 = P[(size_t)(grp * 9 + j + 1) * TOT2 + idx2];
        float2 v2 = P[(size_t)(grp * 9 + j + 2) * TOT2 + idx2];
        a0.x += v0.x; a0.y += v0.y;
        a1.x += v1.x; a1.y += v1.y;
        a2.x += v2.x; a2.y += v2.y;
    }
    red[grp][e2] = make_float2((a0.x + a1.x) + a2.x, (a0.y + a1.y) + a2.y);
    __syncthreads();
    if (tid < 64) {
        float sx = (red[0][e2].x + red[1][e2].x) + (red[2][e2].x + red[3][e2].x);
        float sy = (red[0][e2].y + red[1][e2].y) + (red[2][e2].y + red[3][e2].y);
        float sq = sx * sx + sy * sy;
        sq += __shfl_xor_sync(0xffffffffu, sq, 4);
        sq += __shfl_xor_sync(0xffffffffu, sq, 2);
        sq += __shfl_xor_sync(0xffffffffu, sq, 1);
        float scale = sq / ((1.0f + sq) * sqrtf(sq + 1e-9f));
        float vx = sx * scale, vy = sy * scale;
        int idx = idx2 * 2;
        if (t == 2) {
            *(float2*)(out + idx) = make_float2(vx, vy);
        } else {
            int b = idx / NDIM;
            int ou = idx - b * NDIM;           // even; ou+1 same b
            __nv_bfloat16 hx, lx, hy, ly;
            split_bf16(vx, hx, lx);
            split_bf16(vy, hy, ly);
            g_vT_hi[(size_t)ou * BATCH + b] = hx;
            g_vT_lo[(size_t)ou * BATCH + b] = lx;
            g_vT_hi[(size_t)(ou + 1) * BATCH + b] = hy;
            g_vT_lo[(size_t)(ou + 1) * BATCH + b] = ly;
        }
    }
}

// ---------------------------------------------------------------------------
// M-GEMM (M[ik,ou] = inpT @ vT^T) + fused b-update + fused Wc build for t+1.
// grid 144, one-shot staging + progressive waits.
// ---------------------------------------------------------------------------
__global__ void __launch_bounds__(256, 1)
gemm_m(const float* __restrict__ W, int t) {
    extern __shared__ char sm[];
    __shared__ float c_s[8][10];
    uint32_t sb = smem_to_u32(sm);
    int tid = threadIdx.x, lane = tid & 31, wid = tid >> 5;
    int warp_m = wid & 3, warp_n = wid >> 2;
    int m0 = blockIdx.x * 64;

    #pragma unroll
    for (int c = 0; c < 4; c++) {
        int kb = c * 64;
        #pragma unroll
        for (int r = 0; r < 2; r++) {
            int e = tid + (r << 8);
            int row = e >> 3, j = e & 7;
            cp16(sb + swz(SG_AH + c * 8192, row, j),
                 g_inpT_hi + (size_t)(m0 + row) * BATCH + kb + j * 8);
        }
        #pragma unroll
        for (int r = 0; r < 5; r++) {
            int e = tid + (r << 8);
            int row = e >> 3, j = e & 7;
            cp16(sb + swz(SG_BH + c * 20480, row, j),
                 g_vT_hi + (size_t)row * BATCH + kb + j * 8);
        }
        cp_commit();
    }
    #pragma unroll
    for (int c = 0; c < 4; c++) {
        #pragma unroll
        for (int r = 0; r < 5; r++) {
            int e = tid + (r << 8);
            int row = e >> 3, j = e & 7;
            cp16(sb + swz(SG_BL + c * 20480, row, j),
                 g_vT_lo + (size_t)row * BATCH + c * 64 + j * 8);
        }
        cp_commit();
    }
    #pragma unroll
    for (int c = 0; c < 4; c++) {
        #pragma unroll
        for (int r = 0; r < 2; r++) {
            int e = tid + (r << 8);
            int row = e >> 3, j = e & 7;
            cp16(sb + swz(SG_AL + c * 8192, row, j),
                 g_inpT_lo + (size_t)(m0 + row) * BATCH + c * 64 + j * 8);
        }
        cp_commit();
    }

    float acc[10][4];
    #pragma unroll
    for (int nt = 0; nt < 10; nt++)
        #pragma unroll
        for (int r = 0; r < 4; r++) acc[nt][r] = 0.f;

    int a_row_l = ((lane >> 3) & 1) * 8 + (lane & 7);
    int a_c16_l = lane >> 4;
    int b_dn_l  = ((lane >> 4) & 1) * 8 + (lane & 7);
    int b_c16_l = (lane >> 3) & 1;

    PROGRESSIVE_MAINLOOP();

    // Stage M tile [64][160] fp32 in smem (reuses staging space).
    __syncthreads();
    float* M_s = (float*)sm;
    int r_l = lane >> 2, c_l = (lane & 3) * 2;
    int row = warp_m * 16 + r_l;
    #pragma unroll
    for (int nt = 0; nt < 10; nt++) {
        int col = warp_n * 80 + nt * 8 + c_l;
        *(float2*)(M_s + row * NDIM + col) = make_float2(acc[nt][0], acc[nt][1]);
        *(float2*)(M_s + (row + 8) * NDIM + col) = make_float2(acc[nt][2], acc[nt][3]);
    }
    __syncthreads();

    // b-update: delta[i,o] = (1/B) sum_{k,u} W[i,o,u,k]*M[i8+k][o16+u]
    #pragma unroll
    for (int ee = 0; ee < 10; ee++) {
        int e = wid * 10 + ee;
        int i_rel = e / 10, o = e - i_rel * 10;
        int i = blockIdx.x * 8 + i_rel;
        float sum = 0.f;
        #pragma unroll
        for (int j = 0; j < 4; j++) {
            int f = lane + (j << 5);
            int k = f >> 4, u = f & 15;
            sum = fmaf(W[(size_t)i * 1280 + (o << 7) + (u << 3) + k],
                       M_s[(i_rel * 8 + k) * NDIM + o * 16 + u], sum);
        }
        #pragma unroll
        for (int off = 16; off; off >>= 1)
            sum += __shfl_xor_sync(0xffffffffu, sum, off);
        if (lane == 0) {
            float d = sum * (1.0f / (float)BATCH);
            int gw = i * OUTCH + o;
            float nb = (t == 0) ? d : (g_b[gw] + d);
            g_b[gw] = nb;
        }
    }
    __syncthreads();

    // Fused Wc build for iteration t+1: this CTA owns capsules 8*cta..8*cta+7
    // == chunk cta, and just wrote their g_b rows.
    if (tid < 8) {
        int i = blockIdx.x * 8 + tid;
        float bv[OUTCH], m = -1e30f;
        #pragma unroll
        for (int o = 0; o < OUTCH; o++) {
            bv[o] = g_b[i * OUTCH + o];
            m = fmaxf(m, bv[o]);
        }
        float sum = 0.f;
        #pragma unroll
        for (int o = 0; o < OUTCH; o++) { bv[o] = expf(bv[o] - m); sum += bv[o]; }
        float inv = 1.0f / sum;
        #pragma unroll
        for (int o = 0; o < OUTCH; o++) c_s[tid][o] = bv[o] * inv;
    }
    __syncthreads();
    wc_body(W, blockIdx.x, c_s, tid);
}

// ---------------------------------------------------------------------------
extern "C" void kernel_launch(void* const* d_in, const int* in_sizes, int n_in,
                              void* d_out, int out_size) {
    const float* inp = (const float*)d_in[0];  // [256,1152,8]
    const float* W   = (const float*)d_in[1];  // [1152,10,16,8]
    float* out = (float*)d_out;                // [256,10,16]

    cudaFuncSetAttribute(gemm_s, cudaFuncAttributeMaxDynamicSharedMemorySize, SG_TOT);
    cudaFuncSetAttribute(gemm_m, cudaFuncAttributeMaxDynamicSharedMemorySize, SG_TOT);

    conv_inp<<<dim3(KDIM / 32, BATCH / 32), dim3(32, 8)>>>(inp);
    wc_tiled0<<<NCHUNK, 256>>>(W);

    for (int t = 0; t < 3; t++) {
        gemm_s<<<dim3(4, SPLITS_S), 256, SG_TOT>>>(0);
        squash_k<<<BATCH * NDIM / 128, 256>>>(out, t);
        if (t < 2)
            gemm_m<<<KDIM / 64, 256, SG_TOT>>>(W, t);   // + b-update + Wc(t+1)
    }
}

// round 12
// speedup vs baseline: 1.1365x; 1.0016x over previous
#include <cuda_runtime.h>
#include <cuda_bf16.h>
#include <cstdint>

// CapsNet dynamic routing. u_hat never materialized; bf16 hi/lo 3-pass GEMMs
// on mma.sync (m16n8k16, fp32 accum). All GEMM operands pre-swizzled and
// chunk-tiled in global memory -> loaded with cp.async.bulk (1 instr / tile)
// + mbarrier progressive waits. Wc-build for t+1 fused into gemm_m(t).
//   inp: [256,1152,8] fp32, W: [1152,10,16,8] fp32, out v: [256,10,16] fp32
//
// All __device__ globals referenced only inside device code (host-passed
// __device__ symbols silently resolve to ATS host memory on GB300).

#define BATCH   256
#define INCH    1152
#define INU     8
#define OUTCH   10
#define OUTU    16
#define KDIM    (INCH*INU)     // 9216
#define NDIM    (OUTCH*OUTU)   // 160
#define NCHUNK  144            // 64-k chunks (8 capsules each)
#define SPLITS_S 36            // s-GEMM K splits (4 chunks = 256 K per CTA)

// Swizzled-tile byte offset for element (row, col) in a (rows x 64-bf16) tile:
//   off = row*128 + ((col>>3 ^ (row&7))<<4) + (col&7)*2
// Identical to the smem layout the GEMMs ldmatrix from.

// ---------------- device globals (pre-swizzled tile storage) ---------------
__device__ __align__(16) unsigned char g_A_hi[NCHUNK * 4 * 8192];   // [chunk][mblk][64x128B]
__device__ __align__(16) unsigned char g_A_lo[NCHUNK * 4 * 8192];
__device__ __align__(16) unsigned char g_AT_hi[4 * NCHUNK * 8192];  // [kc][ikblk][64x128B]
__device__ __align__(16) unsigned char g_AT_lo[4 * NCHUNK * 8192];
__device__ __align__(16) unsigned char g_Bt_hi[NCHUNK * 20480];     // [chunk][160x128B]
__device__ __align__(16) unsigned char g_Bt_lo[NCHUNK * 20480];
__device__ __align__(16) unsigned char g_vT2_hi[4 * 20480];         // [kc][160x128B]
__device__ __align__(16) unsigned char g_vT2_lo[4 * 20480];
__device__ float g_part_s[SPLITS_S * BATCH * NDIM];                 // 5.9 MB
__device__ float g_b[INCH * OUTCH];

__device__ __forceinline__ uint32_t smem_to_u32(const void* p) {
    uint32_t a;
    asm("{ .reg .u64 t; cvta.to.shared.u64 t, %1; cvt.u32.u64 %0, t; }"
        : "=r"(a) : "l"(p));
    return a;
}
__device__ __forceinline__ void split_bf16(float x, __nv_bfloat16& h, __nv_bfloat16& l) {
    h = __float2bfloat16(x);
    l = __float2bfloat16(x - __bfloat162float(h));
}
__device__ __forceinline__ void ldsm4(uint32_t& r0, uint32_t& r1, uint32_t& r2,
                                      uint32_t& r3, uint32_t addr) {
    asm volatile("ldmatrix.sync.aligned.m8n8.x4.shared.b16 {%0,%1,%2,%3}, [%4];"
                 : "=r"(r0), "=r"(r1), "=r"(r2), "=r"(r3) : "r"(addr));
}
__device__ __forceinline__ void mma16816(float* d, const uint32_t* a,
                                         const uint32_t* b) {
    asm volatile(
        "mma.sync.aligned.m16n8k16.row.col.f32.bf16.bf16.f32 "
        "{%0,%1,%2,%3}, {%4,%5,%6,%7}, {%8,%9}, {%0,%1,%2,%3};"
        : "+f"(d[0]), "+f"(d[1]), "+f"(d[2]), "+f"(d[3])
        : "r"(a[0]), "r"(a[1]), "r"(a[2]), "r"(a[3]), "r"(b[0]), "r"(b[1]));
}

// ---- mbarrier + bulk-copy primitives (sm_90 baseline PTX) ----
#define MBAR_INIT(a, c) \
    asm volatile("mbarrier.init.shared.b64 [%0], %1;" \
                 :: "r"((uint32_t)(a)), "r"((uint32_t)(c)) : "memory")
#define MBAR_EXPECT(a, tx) \
    asm volatile("mbarrier.arrive.expect_tx.shared.b64 _, [%0], %1;" \
                 :: "r"((uint32_t)(a)), "r"((uint32_t)(tx)) : "memory")
#define MBAR_WAIT(a, ph) do { \
    uint32_t _mb = (uint32_t)(a); uint32_t _p = (uint32_t)(ph); uint32_t _d; \
    asm volatile("{\n\t.reg .pred p;\n\t" \
        "mbarrier.try_wait.parity.acquire.cta.shared::cta.b64 p, [%1], %2;\n\t" \
        "selp.b32 %0, 1, 0, p;\n\t}" : "=r"(_d) : "r"(_mb), "r"(_p) : "memory"); \
    if (!_d) { \
        asm volatile("{\n\t.reg .pred P1;\n\tWL_%=:\n\t" \
            "mbarrier.try_wait.parity.acquire.cta.shared::cta.b64 P1, [%0], %1, 0x989680;\n\t" \
            "@P1 bra.uni WD_%=;\n\tbra.uni WL_%=;\n\tWD_%=:\n\t}" \
            :: "r"(_mb), "r"(_p) : "memory"); \
    } } while (0)
__device__ __forceinline__ void bulkcp(uint32_t dst, const void* src,
                                       uint32_t bytes, uint32_t mbar) {
    asm volatile(
        "cp.async.bulk.shared::cluster.global.mbarrier::complete_tx::bytes "
        "[%0], [%1], %2, [%3];"
        :: "r"(dst), "l"(src), "r"(bytes), "r"(mbar) : "memory");
}

// ---------------------------------------------------------------------------
// One-time: inp fp32 -> bf16 hi/lo into BOTH pre-swizzled tile layouts.
// grid (144 ikblk, 4 bblk), 256 threads. Tile = 64 b x 64 ik.
// ---------------------------------------------------------------------------
__global__ void conv_inp(const float* __restrict__ inp) {
    __shared__ unsigned short sh_hi[64][72];
    __shared__ unsigned short sh_lo[64][72];
    int ik0 = blockIdx.x * 64, b0 = blockIdx.y * 64;
    int tid = threadIdx.x;

    #pragma unroll
    for (int it = 0; it < 16; it++) {
        int row = it * 4 + (tid >> 6);     // b within tile
        int col = tid & 63;                // ik within tile
        float x = inp[(size_t)(b0 + row) * KDIM + ik0 + col];
        __nv_bfloat16 h, l;
        split_bf16(x, h, l);
        sh_hi[row][col] = __bfloat16_as_ushort(h);
        sh_lo[row][col] = __bfloat16_as_ushort(l);
    }
    __syncthreads();

    unsigned char* Ah = g_A_hi + ((size_t)blockIdx.x * 4 + blockIdx.y) * 8192;
    unsigned char* Al = g_A_lo + ((size_t)blockIdx.x * 4 + blockIdx.y) * 8192;
    unsigned char* Th = g_AT_hi + ((size_t)blockIdx.y * NCHUNK + blockIdx.x) * 8192;
    unsigned char* Tl = g_AT_lo + ((size_t)blockIdx.y * NCHUNK + blockIdx.x) * 8192;

    #pragma unroll
    for (int k = 0; k < 4; k++) {
        int w = tid + (k << 8);            // 0..1023 uint2 slots
        int r = w >> 4, g = w & 15;
        uint32_t off = (uint32_t)r * 128 + ((((g >> 1) ^ (r & 7))) << 4) + (g & 1) * 8;
        // A layout: row=b, col=ik (4 consecutive ik = g*4..g*4+3)
        {
            int c0 = g * 4;
            uint2 vh, vl;
            vh.x = (uint32_t)sh_hi[r][c0] | ((uint32_t)sh_hi[r][c0+1] << 16);
            vh.y = (uint32_t)sh_hi[r][c0+2] | ((uint32_t)sh_hi[r][c0+3] << 16);
            vl.x = (uint32_t)sh_lo[r][c0] | ((uint32_t)sh_lo[r][c0+1] << 16);
            vl.y = (uint32_t)sh_lo[r][c0+2] | ((uint32_t)sh_lo[r][c0+3] << 16);
            *(uint2*)(Ah + off) = vh;
            *(uint2*)(Al + off) = vl;
        }
        // AT layout: row=ik, col=b (4 consecutive b)
        {
            int c0 = g * 4;
            uint2 vh, vl;
            vh.x = (uint32_t)sh_hi[c0][r] | ((uint32_t)sh_hi[c0+1][r] << 16);
            vh.y = (uint32_t)sh_hi[c0+2][r] | ((uint32_t)sh_hi[c0+3][r] << 16);
            vl.x = (uint32_t)sh_lo[c0][r] | ((uint32_t)sh_lo[c0+1][r] << 16);
            vl.y = (uint32_t)sh_lo[c0+2][r] | ((uint32_t)sh_lo[c0+3][r] << 16);
            *(uint2*)(Th + off) = vh;
            *(uint2*)(Tl + off) = vl;
        }
    }
}

// ---------------------------------------------------------------------------
// Wc body: g_Bt[chunk] (pre-swizzled 160x128B) = c[i,o]*W[i,o,u,k] hi/lo.
// ---------------------------------------------------------------------------
__device__ __forceinline__ void wc_body(const float* __restrict__ W, int chunk,
                                        const float (*c_s)[10], int tid) {
    const float4* W4 = (const float4*)(W + (size_t)chunk * 8 * 1280);
    unsigned char* bh = g_Bt_hi + (size_t)chunk * 20480;
    unsigned char* bl = g_Bt_lo + (size_t)chunk * 20480;
    #pragma unroll
    for (int r = 0; r < 10; r++) {
        int q = tid + (r << 8);              // 0..2559 float4s (8 caps x 320)
        int i_off = q / 320;
        int rem = q - i_off * 320;
        int o = rem >> 5;
        int rem2 = rem & 31;
        int u = rem2 >> 1, kh = rem2 & 1;
        float4 f = W4[q];
        float cv = c_s[i_off][o];
        __nv_bfloat16 h0,l0,h1,l1,h2,l2,h3,l3;
        split_bf16(f.x * cv, h0, l0);
        split_bf16(f.y * cv, h1, l1);
        split_bf16(f.z * cv, h2, l2);
        split_bf16(f.w * cv, h3, l3);
        uint2 ph, pl;
        ph.x = (uint32_t)__bfloat16_as_ushort(h0) | ((uint32_t)__bfloat16_as_ushort(h1) << 16);
        ph.y = (uint32_t)__bfloat16_as_ushort(h2) | ((uint32_t)__bfloat16_as_ushort(h3) << 16);
        pl.x = (uint32_t)__bfloat16_as_ushort(l0) | ((uint32_t)__bfloat16_as_ushort(l1) << 16);
        pl.y = (uint32_t)__bfloat16_as_ushort(l2) | ((uint32_t)__bfloat16_as_ushort(l3) << 16);
        int row = o * 16 + u;
        uint32_t off = (uint32_t)row * 128 + ((i_off ^ (row & 7)) << 4) + kh * 8;
        *(uint2*)(bh + off) = ph;
        *(uint2*)(bl + off) = pl;
    }
}

// Standalone Wc build, t=0 only (c = 0.1 constant).
__global__ void wc_tiled0(const float* __restrict__ W) {
    __shared__ float c_s[8][10];
    int tid = threadIdx.x;
    if (tid < 80) c_s[tid / 10][tid % 10] = 0.1f;
    __syncthreads();
    wc_body(W, blockIdx.x, c_s, tid);
}

// ---------------------------------------------------------------------------
// Staging layout (224 KB): AH 4x8192 @0, AL @32768, BH 4x20480 @65536,
// BL @147456. 12 mbarriers: 0..3 = (Ah+Bh)_c, 4..7 = Bl_c, 8..11 = Al_c.
// ---------------------------------------------------------------------------
#define SG_AH 0
#define SG_AL 32768
#define SG_BH 65536
#define SG_BL 147456
#define SG_TOT 229376

__device__ __forceinline__ uint32_t swz(uint32_t base, int row, int col16) {
    return base + (uint32_t)row * 128 + (uint32_t)((col16 ^ (row & 7)) << 4);
}

#define DO_CHUNK(aBase, bBase)                                                \
    do {                                                                      \
        _Pragma("unroll")                                                     \
        for (int ks = 0; ks < 4; ks++) {                                      \
            uint32_t af[4], bf[10][2];                                        \
            int arow = warp_m * 16 + a_row_l;                                 \
            ldsm4(af[0], af[1], af[2], af[3],                                 \
                  sb + swz((aBase), arow, (ks << 1) | a_c16_l));              \
            _Pragma("unroll")                                                 \
            for (int p = 0; p < 5; p++) {                                     \
                int brow = warp_n * 80 + p * 16 + b_dn_l;                     \
                ldsm4(bf[2*p][0], bf[2*p][1], bf[2*p+1][0], bf[2*p+1][1],     \
                      sb + swz((bBase), brow, (ks << 1) | b_c16_l));          \
            }                                                                 \
            _Pragma("unroll")                                                 \
            for (int nt = 0; nt < 10; nt++)                                   \
                mma16816(acc[nt], af, bf[nt]);                                \
        }                                                                     \
    } while (0)

#define PROGRESSIVE_MAINLOOP(mb0)                                                      \
    MBAR_WAIT((mb0) + 0*8, 0);  DO_CHUNK(SG_AH + 0*8192, SG_BH + 0*20480);             \
    MBAR_WAIT((mb0) + 1*8, 0);  DO_CHUNK(SG_AH + 1*8192, SG_BH + 1*20480);             \
    MBAR_WAIT((mb0) + 2*8, 0);  DO_CHUNK(SG_AH + 2*8192, SG_BH + 2*20480);             \
    MBAR_WAIT((mb0) + 3*8, 0);  DO_CHUNK(SG_AH + 3*8192, SG_BH + 3*20480);             \
    MBAR_WAIT((mb0) + 4*8, 0);  DO_CHUNK(SG_AH + 0*8192, SG_BL + 0*20480);             \
    MBAR_WAIT((mb0) + 5*8, 0);  DO_CHUNK(SG_AH + 1*8192, SG_BL + 1*20480);             \
    MBAR_WAIT((mb0) + 6*8, 0);  DO_CHUNK(SG_AH + 2*8192, SG_BL + 2*20480);             \
    MBAR_WAIT((mb0) + 7*8, 0);  DO_CHUNK(SG_AH + 3*8192, SG_BL + 3*20480);             \
    MBAR_WAIT((mb0) + 8*8, 0);  DO_CHUNK(SG_AL + 0*8192, SG_BH + 0*20480);             \
    MBAR_WAIT((mb0) + 9*8, 0);  DO_CHUNK(SG_AL + 1*8192, SG_BH + 1*20480);             \
    MBAR_WAIT((mb0) + 10*8, 0); DO_CHUNK(SG_AL + 2*8192, SG_BH + 2*20480);             \
    MBAR_WAIT((mb0) + 11*8, 0); DO_CHUNK(SG_AL + 3*8192, SG_BH + 3*20480);

// ---------------------------------------------------------------------------
// s-GEMM: grid (4 Mtiles, 36 Ksplits) = 144 CTAs, 256 thr, 8 warps (4M x 2N).
// ---------------------------------------------------------------------------
__global__ void __launch_bounds__(256, 1)
gemm_s(int t_unused) {
    extern __shared__ char sm[];
    __shared__ __align__(8) uint64_t mbar[12];
    uint32_t sb = smem_to_u32(sm);
    uint32_t mb0 = smem_to_u32(mbar);
    int tid = threadIdx.x, lane = tid & 31, wid = tid >> 5;
    int warp_m = wid & 3, warp_n = wid >> 2;
    int bx = blockIdx.x;                     // mblk
    int chunk0 = blockIdx.y * 4;

    if (tid == 0) {
        #pragma unroll
        for (int i = 0; i < 12; i++) MBAR_INIT(mb0 + i * 8, 1);
    }
    __syncthreads();
    if (tid == 0) {
        #pragma unroll
        for (int c = 0; c < 4; c++) {
            uint32_t m = mb0 + c * 8;
            MBAR_EXPECT(m, 8192 + 20480);
            bulkcp(sb + SG_AH + c * 8192,
                   g_A_hi + ((size_t)(chunk0 + c) * 4 + bx) * 8192, 8192, m);
            bulkcp(sb + SG_BH + c * 20480,
                   g_Bt_hi + (size_t)(chunk0 + c) * 20480, 20480, m);
        }
        #pragma unroll
        for (int c = 0; c < 4; c++) {
            uint32_t m = mb0 + (4 + c) * 8;
            MBAR_EXPECT(m, 20480);
            bulkcp(sb + SG_BL + c * 20480,
                   g_Bt_lo + (size_t)(chunk0 + c) * 20480, 20480, m);
        }
        #pragma unroll
        for (int c = 0; c < 4; c++) {
            uint32_t m = mb0 + (8 + c) * 8;
            MBAR_EXPECT(m, 8192);
            bulkcp(sb + SG_AL + c * 8192,
                   g_A_lo + ((size_t)(chunk0 + c) * 4 + bx) * 8192, 8192, m);
        }
    }

    float acc[10][4];
    #pragma unroll
    for (int nt = 0; nt < 10; nt++)
        #pragma unroll
        for (int r = 0; r < 4; r++) acc[nt][r] = 0.f;

    int a_row_l = ((lane >> 3) & 1) * 8 + (lane & 7);
    int a_c16_l = lane >> 4;
    int b_dn_l  = ((lane >> 4) & 1) * 8 + (lane & 7);
    int b_c16_l = (lane >> 3) & 1;

    PROGRESSIVE_MAINLOOP(mb0);

    float* out = g_part_s + (size_t)blockIdx.y * (BATCH * NDIM);
    int r_l = lane >> 2, c_l = (lane & 3) * 2;
    int row = bx * 64 + warp_m * 16 + r_l;
    #pragma unroll
    for (int nt = 0; nt < 10; nt++) {
        int col = warp_n * 80 + nt * 8 + c_l;
        *(float2*)(out + (size_t)row * NDIM + col) = make_float2(acc[nt][0], acc[nt][1]);
        *(float2*)(out + (size_t)(row + 8) * NDIM + col) = make_float2(acc[nt][2], acc[nt][3]);
    }
}

// ---------------------------------------------------------------------------
// Split-K reduce + squash, float4 loads: 320 blocks x 256 thr =
// 32 float4-elems x 8 uneven split-groups (5,5,5,5,4,4,4,4).
// ---------------------------------------------------------------------------
__global__ void squash_k(float* __restrict__ out, int t) {
    __shared__ float4 red[8][32];
    int tid = threadIdx.x;
    int e4 = tid & 31;
    int grp = tid >> 5;                        // 0..7
    int idx4 = blockIdx.x * 32 + e4;           // float4 index (0..10239)
    const float4* P = (const float4*)g_part_s; // [36][10240]
    int start = (grp < 4) ? grp * 5 : 20 + (grp - 4) * 4;
    int cnt = (grp < 4) ? 5 : 4;

    float4 a = make_float4(0.f, 0.f, 0.f, 0.f), b4 = a;
    #pragma unroll 5
    for (int j = 0; j < cnt; j++) {
        float4 v = P[(size_t)(start + j) * 10240 + idx4];
        if (j & 1) { b4.x += v.x; b4.y += v.y; b4.z += v.z; b4.w += v.w; }
        else       { a.x += v.x;  a.y += v.y;  a.z += v.z;  a.w += v.w;  }
    }
    red[grp][e4] = make_float4(a.x + b4.x, a.y + b4.y, a.z + b4.z, a.w + b4.w);
    __syncthreads();

    if (tid < 32) {
        float4 s = make_float4(0.f, 0.f, 0.f, 0.f);
        #pragma unroll
        for (int g = 0; g < 8; g += 2) {
            float4 u = red[g][tid], w = red[g + 1][tid];
            s.x += u.x + w.x; s.y += u.y + w.y;
            s.z += u.z + w.z; s.w += u.w + w.w;
        }
        float sq = s.x * s.x + s.y * s.y + s.z * s.z + s.w * s.w;
        sq += __shfl_xor_sync(0xffffffffu, sq, 1);
        sq += __shfl_xor_sync(0xffffffffu, sq, 2);
        float scale = sq / ((1.0f + sq) * sqrtf(sq + 1e-9f));
        float4 v = make_float4(s.x * scale, s.y * scale, s.z * scale, s.w * scale);
        int idx = (blockIdx.x * 32 + tid) * 4;
        if (t == 2) {
            *(float4*)(out + idx) = v;
        } else {
            int b = idx / NDIM;
            int ou0 = idx - b * NDIM;          // 4|160 so same b for all 4
            int kc = b >> 6, col = b & 63;
            float vv[4] = {v.x, v.y, v.z, v.w};
            #pragma unroll
            for (int j = 0; j < 4; j++) {
                int ou = ou0 + j;
                uint32_t off = (uint32_t)kc * 20480 + ou * 128
                             + (((col >> 3) ^ (ou & 7)) << 4) + (col & 7) * 2;
                __nv_bfloat16 h, l;
                split_bf16(vv[j], h, l);
                *(unsigned short*)(g_vT2_hi + off) = __bfloat16_as_ushort(h);
                *(unsigned short*)(g_vT2_lo + off) = __bfloat16_as_ushort(l);
            }
        }
    }
}

// ---------------------------------------------------------------------------
// M-GEMM (M[ik,ou] = inpT @ vT^T) + fused b-update + fused Wc build for t+1.
// grid 144, bulk-copy staging + progressive mbarrier waits.
// ---------------------------------------------------------------------------
__global__ void __launch_bounds__(256, 1)
gemm_m(const float* __restrict__ W, int t) {
    extern __shared__ char sm[];
    __shared__ __align__(8) uint64_t mbar[12];
    __shared__ float c_s[8][10];
    uint32_t sb = smem_to_u32(sm);
    uint32_t mb0 = smem_to_u32(mbar);
    int tid = threadIdx.x, lane = tid & 31, wid = tid >> 5;
    int warp_m = wid & 3, warp_n = wid >> 2;
    int cta = blockIdx.x;

    if (tid == 0) {
        #pragma unroll
        for (int i = 0; i < 12; i++) MBAR_INIT(mb0 + i * 8, 1);
    }
    __syncthreads();
    if (tid == 0) {
        #pragma unroll
        for (int c = 0; c < 4; c++) {
            uint32_t m = mb0 + c * 8;
            MBAR_EXPECT(m, 8192 + 20480);
            bulkcp(sb + SG_AH + c * 8192,
                   g_AT_hi + ((size_t)c * NCHUNK + cta) * 8192, 8192, m);
            bulkcp(sb + SG_BH + c * 20480, g_vT2_hi + (size_t)c * 20480, 20480, m);
        }
        #pragma unroll
        for (int c = 0; c < 4; c++) {
            uint32_t m = mb0 + (4 + c) * 8;
            MBAR_EXPECT(m, 20480);
            bulkcp(sb + SG_BL + c * 20480, g_vT2_lo + (size_t)c * 20480, 20480, m);
        }
        #pragma unroll
        for (int c = 0; c < 4; c++) {
            uint32_t m = mb0 + (8 + c) * 8;
            MBAR_EXPECT(m, 8192);
            bulkcp(sb + SG_AL + c * 8192,
                   g_AT_lo + ((size_t)c * NCHUNK + cta) * 8192, 8192, m);
        }
    }

    float acc[10][4];
    #pragma unroll
    for (int nt = 0; nt < 10; nt++)
        #pragma unroll
        for (int r = 0; r < 4; r++) acc[nt][r] = 0.f;

    int a_row_l = ((lane >> 3) & 1) * 8 + (lane & 7);
    int a_c16_l = lane >> 4;
    int b_dn_l  = ((lane >> 4) & 1) * 8 + (lane & 7);
    int b_c16_l = (lane >> 3) & 1;

    PROGRESSIVE_MAINLOOP(mb0);

    // Stage M tile [64][160] fp32 in smem (reuses staging space).
    __syncthreads();
    float* M_s = (float*)sm;
    int r_l = lane >> 2, c_l = (lane & 3) * 2;
    int row = warp_m * 16 + r_l;
    #pragma unroll
    for (int nt = 0; nt < 10; nt++) {
        int col = warp_n * 80 + nt * 8 + c_l;
        *(float2*)(M_s + row * NDIM + col) = make_float2(acc[nt][0], acc[nt][1]);
        *(float2*)(M_s + (row + 8) * NDIM + col) = make_float2(acc[nt][2], acc[nt][3]);
    }
    __syncthreads();

    // b-update: delta[i,o] = (1/B) sum_{k,u} W[i,o,u,k]*M[i8+k][o16+u]
    #pragma unroll
    for (int ee = 0; ee < 10; ee++) {
        int e = wid * 10 + ee;
        int i_rel = e / 10, o = e - i_rel * 10;
        int i = cta * 8 + i_rel;
        float sum = 0.f;
        #pragma unroll
        for (int j = 0; j < 4; j++) {
            int f = lane + (j << 5);
            int k = f >> 4, u = f & 15;
            sum = fmaf(W[(size_t)i * 1280 + (o << 7) + (u << 3) + k],
                       M_s[(i_rel * 8 + k) * NDIM + o * 16 + u], sum);
        }
        #pragma unroll
        for (int off = 16; off; off >>= 1)
            sum += __shfl_xor_sync(0xffffffffu, sum, off);
        if (lane == 0) {
            float d = sum * (1.0f / (float)BATCH);
            int gw = i * OUTCH + o;
            g_b[gw] = (t == 0) ? d : (g_b[gw] + d);
        }
    }
    __syncthreads();

    // Fused Wc build for iteration t+1 (this CTA owns chunk == cta).
    if (tid < 8) {
        int i = cta * 8 + tid;
        float bv[OUTCH], m = -1e30f;
        #pragma unroll
        for (int o = 0; o < OUTCH; o++) {
            bv[o] = g_b[i * OUTCH + o];
            m = fmaxf(m, bv[o]);
        }
        float sum = 0.f;
        #pragma unroll
        for (int o = 0; o < OUTCH; o++) { bv[o] = expf(bv[o] - m); sum += bv[o]; }
        float inv = 1.0f / sum;
        #pragma unroll
        for (int o = 0; o < OUTCH; o++) c_s[tid][o] = bv[o] * inv;
    }
    __syncthreads();
    wc_body(W, cta, c_s, tid);
}

// ---------------------------------------------------------------------------
extern "C" void kernel_launch(void* const* d_in, const int* in_sizes, int n_in,
                              void* d_out, int out_size) {
    const float* inp = (const float*)d_in[0];  // [256,1152,8]
    const float* W   = (const float*)d_in[1];  // [1152,10,16,8]
    float* out = (float*)d_out;                // [256,10,16]

    cudaFuncSetAttribute(gemm_s, cudaFuncAttributeMaxDynamicSharedMemorySize, SG_TOT);
    cudaFuncSetAttribute(gemm_m, cudaFuncAttributeMaxDynamicSharedMemorySize, SG_TOT);

    conv_inp<<<dim3(NCHUNK, 4), 256>>>(inp);
    wc_tiled0<<<NCHUNK, 256>>>(W);

    for (int t = 0; t < 3; t++) {
        gemm_s<<<dim3(4, SPLITS_S), 256, SG_TOT>>>(0);
        squash_k<<<320, 256>>>(out, t);
        if (t < 2)
            gemm_m<<<NCHUNK, 256, SG_TOT>>>(W, t);   // + b-update + Wc(t+1)
    }
}

// round 13
// speedup vs baseline: 1.1602x; 1.0208x over previous
#include <cuda_runtime.h>
#include <cuda_bf16.h>
#include <cstdint>

// CapsNet dynamic routing. u_hat never materialized; bf16 hi/lo 3-pass GEMMs
// on mma.sync (m16n8k16, fp32 accum). Pre-swizzled operands + cp.async.bulk.
// squash fused into gemm_s via per-Mtile arrival counters; Wc(t+1) fused into
// gemm_m(t); Wc(0) fused into conv_inp. 6 launches total.
//   inp: [256,1152,8] fp32, W: [1152,10,16,8] fp32, out v: [256,10,16] fp32
//
// All __device__ globals referenced only inside device code (host-passed
// __device__ symbols silently resolve to ATS host memory on GB300).

#define BATCH   256
#define INCH    1152
#define INU     8
#define OUTCH   10
#define OUTU    16
#define KDIM    (INCH*INU)     // 9216
#define NDIM    (OUTCH*OUTU)   // 160
#define NCHUNK  144            // 64-k chunks (8 capsules each)
#define SPLITS_S 36            // s-GEMM K splits (4 chunks = 256 K per CTA)

// ---------------- device globals (pre-swizzled tile storage) ---------------
__device__ __align__(16) unsigned char g_A_hi[NCHUNK * 4 * 8192];   // [chunk][mblk][64x128B]
__device__ __align__(16) unsigned char g_A_lo[NCHUNK * 4 * 8192];
__device__ __align__(16) unsigned char g_AT_hi[4 * NCHUNK * 8192];  // [kc][ikblk][64x128B]
__device__ __align__(16) unsigned char g_AT_lo[4 * NCHUNK * 8192];
__device__ __align__(16) unsigned char g_Bt_hi[NCHUNK * 20480];     // [chunk][160x128B]
__device__ __align__(16) unsigned char g_Bt_lo[NCHUNK * 20480];
__device__ __align__(16) unsigned char g_vT2_hi[4 * 20480];         // [kc][160x128B]
__device__ __align__(16) unsigned char g_vT2_lo[4 * 20480];
__device__ float g_part_s[SPLITS_S * BATCH * NDIM];                 // 5.9 MB
__device__ float g_b[INCH * OUTCH];
__device__ int   g_cnt[4];                                          // per-Mtile arrivals

__device__ __forceinline__ uint32_t smem_to_u32(const void* p) {
    uint32_t a;
    asm("{ .reg .u64 t; cvta.to.shared.u64 t, %1; cvt.u32.u64 %0, t; }"
        : "=r"(a) : "l"(p));
    return a;
}
__device__ __forceinline__ void split_bf16(float x, __nv_bfloat16& h, __nv_bfloat16& l) {
    h = __float2bfloat16(x);
    l = __float2bfloat16(x - __bfloat162float(h));
}
__device__ __forceinline__ void ldsm4(uint32_t& r0, uint32_t& r1, uint32_t& r2,
                                      uint32_t& r3, uint32_t addr) {
    asm volatile("ldmatrix.sync.aligned.m8n8.x4.shared.b16 {%0,%1,%2,%3}, [%4];"
                 : "=r"(r0), "=r"(r1), "=r"(r2), "=r"(r3) : "r"(addr));
}
__device__ __forceinline__ void mma16816(float* d, const uint32_t* a,
                                         const uint32_t* b) {
    asm volatile(
        "mma.sync.aligned.m16n8k16.row.col.f32.bf16.bf16.f32 "
        "{%0,%1,%2,%3}, {%4,%5,%6,%7}, {%8,%9}, {%0,%1,%2,%3};"
        : "+f"(d[0]), "+f"(d[1]), "+f"(d[2]), "+f"(d[3])
        : "r"(a[0]), "r"(a[1]), "r"(a[2]), "r"(a[3]), "r"(b[0]), "r"(b[1]));
}

// ---- mbarrier + bulk-copy primitives (sm_90 baseline PTX) ----
#define MBAR_INIT(a, c) \
    asm volatile("mbarrier.init.shared.b64 [%0], %1;" \
                 :: "r"((uint32_t)(a)), "r"((uint32_t)(c)) : "memory")
#define MBAR_EXPECT(a, tx) \
    asm volatile("mbarrier.arrive.expect_tx.shared.b64 _, [%0], %1;" \
                 :: "r"((uint32_t)(a)), "r"((uint32_t)(tx)) : "memory")
#define MBAR_WAIT(a, ph) do { \
    uint32_t _mb = (uint32_t)(a); uint32_t _p = (uint32_t)(ph); uint32_t _d; \
    asm volatile("{\n\t.reg .pred p;\n\t" \
        "mbarrier.try_wait.parity.acquire.cta.shared::cta.b64 p, [%1], %2;\n\t" \
        "selp.b32 %0, 1, 0, p;\n\t}" : "=r"(_d) : "r"(_mb), "r"(_p) : "memory"); \
    if (!_d) { \
        asm volatile("{\n\t.reg .pred P1;\n\tWL_%=:\n\t" \
            "mbarrier.try_wait.parity.acquire.cta.shared::cta.b64 P1, [%0], %1, 0x989680;\n\t" \
            "@P1 bra.uni WD_%=;\n\tbra.uni WL_%=;\n\tWD_%=:\n\t}" \
            :: "r"(_mb), "r"(_p) : "memory"); \
    } } while (0)
__device__ __forceinline__ void bulkcp(uint32_t dst, const void* src,
                                       uint32_t bytes, uint32_t mbar) {
    asm volatile(
        "cp.async.bulk.shared::cluster.global.mbarrier::complete_tx::bytes "
        "[%0], [%1], %2, [%3];"
        :: "r"(dst), "l"(src), "r"(bytes), "r"(mbar) : "memory");
}

// ---------------------------------------------------------------------------
// Wc body: g_Bt[chunk] (pre-swizzled 160x128B) = c[i,o]*W[i,o,u,k] hi/lo.
// ---------------------------------------------------------------------------
__device__ __forceinline__ void wc_body(const float* __restrict__ W, int chunk,
                                        const float (*c_s)[10], int tid) {
    const float4* W4 = (const float4*)(W + (size_t)chunk * 8 * 1280);
    unsigned char* bh = g_Bt_hi + (size_t)chunk * 20480;
    unsigned char* bl = g_Bt_lo + (size_t)chunk * 20480;
    #pragma unroll
    for (int r = 0; r < 10; r++) {
        int q = tid + (r << 8);              // 0..2559 float4s (8 caps x 320)
        int i_off = q / 320;
        int rem = q - i_off * 320;
        int o = rem >> 5;
        int rem2 = rem & 31;
        int u = rem2 >> 1, kh = rem2 & 1;
        float4 f = W4[q];
        float cv = c_s[i_off][o];
        __nv_bfloat16 h0,l0,h1,l1,h2,l2,h3,l3;
        split_bf16(f.x * cv, h0, l0);
        split_bf16(f.y * cv, h1, l1);
        split_bf16(f.z * cv, h2, l2);
        split_bf16(f.w * cv, h3, l3);
        uint2 ph, pl;
        ph.x = (uint32_t)__bfloat16_as_ushort(h0) | ((uint32_t)__bfloat16_as_ushort(h1) << 16);
        ph.y = (uint32_t)__bfloat16_as_ushort(h2) | ((uint32_t)__bfloat16_as_ushort(h3) << 16);
        pl.x = (uint32_t)__bfloat16_as_ushort(l0) | ((uint32_t)__bfloat16_as_ushort(l1) << 16);
        pl.y = (uint32_t)__bfloat16_as_ushort(l2) | ((uint32_t)__bfloat16_as_ushort(l3) << 16);
        int row = o * 16 + u;
        uint32_t off = (uint32_t)row * 128 + ((i_off ^ (row & 7)) << 4) + kh * 8;
        *(uint2*)(bh + off) = ph;
        *(uint2*)(bl + off) = pl;
    }
}

// ---------------------------------------------------------------------------
// One-time: inp -> bf16 hi/lo pre-swizzled tiles (both layouts); fused Wc(0)
// for by==0 blocks; resets g_cnt. grid (144, 4), 256 threads.
// ---------------------------------------------------------------------------
__global__ void conv_inp(const float* __restrict__ inp, const float* __restrict__ W) {
    __shared__ unsigned short sh_hi[64][72];
    __shared__ unsigned short sh_lo[64][72];
    __shared__ float c_s[8][10];
    int ik0 = blockIdx.x * 64, b0 = blockIdx.y * 64;
    int tid = threadIdx.x;

    if (blockIdx.x == 0 && blockIdx.y == 0 && tid < 4) g_cnt[tid] = 0;

    #pragma unroll
    for (int it = 0; it < 16; it++) {
        int row = it * 4 + (tid >> 6);     // b within tile
        int col = tid & 63;                // ik within tile
        float x = inp[(size_t)(b0 + row) * KDIM + ik0 + col];
        __nv_bfloat16 h, l;
        split_bf16(x, h, l);
        sh_hi[row][col] = __bfloat16_as_ushort(h);
        sh_lo[row][col] = __bfloat16_as_ushort(l);
    }
    __syncthreads();

    unsigned char* Ah = g_A_hi + ((size_t)blockIdx.x * 4 + blockIdx.y) * 8192;
    unsigned char* Al = g_A_lo + ((size_t)blockIdx.x * 4 + blockIdx.y) * 8192;
    unsigned char* Th = g_AT_hi + ((size_t)blockIdx.y * NCHUNK + blockIdx.x) * 8192;
    unsigned char* Tl = g_AT_lo + ((size_t)blockIdx.y * NCHUNK + blockIdx.x) * 8192;

    #pragma unroll
    for (int k = 0; k < 4; k++) {
        int w = tid + (k << 8);            // 0..1023 uint2 slots
        int r = w >> 4, g = w & 15;
        uint32_t off = (uint32_t)r * 128 + ((((g >> 1) ^ (r & 7))) << 4) + (g & 1) * 8;
        {
            int c0 = g * 4;
            uint2 vh, vl;
            vh.x = (uint32_t)sh_hi[r][c0] | ((uint32_t)sh_hi[r][c0+1] << 16);
            vh.y = (uint32_t)sh_hi[r][c0+2] | ((uint32_t)sh_hi[r][c0+3] << 16);
            vl.x = (uint32_t)sh_lo[r][c0] | ((uint32_t)sh_lo[r][c0+1] << 16);
            vl.y = (uint32_t)sh_lo[r][c0+2] | ((uint32_t)sh_lo[r][c0+3] << 16);
            *(uint2*)(Ah + off) = vh;
            *(uint2*)(Al + off) = vl;
        }
        {
            int c0 = g * 4;
            uint2 vh, vl;
            vh.x = (uint32_t)sh_hi[c0][r] | ((uint32_t)sh_hi[c0+1][r] << 16);
            vh.y = (uint32_t)sh_hi[c0+2][r] | ((uint32_t)sh_hi[c0+3][r] << 16);
            vl.x = (uint32_t)sh_lo[c0][r] | ((uint32_t)sh_lo[c0+1][r] << 16);
            vl.y = (uint32_t)sh_lo[c0+2][r] | ((uint32_t)sh_lo[c0+3][r] << 16);
            *(uint2*)(Th + off) = vh;
            *(uint2*)(Tl + off) = vl;
        }
    }

    // Fused Wc(0): c = 0.1 constant (one block column does it).
    if (blockIdx.y == 0) {
        if (tid < 80) c_s[tid / 10][tid % 10] = 0.1f;
        __syncthreads();
        wc_body(W, blockIdx.x, c_s, tid);
    }
}

// ---------------------------------------------------------------------------
// Staging layout (224 KB): AH 4x8192 @0, AL @32768, BH 4x20480 @65536,
// BL @147456. 12 mbarriers: 0..3 = (Ah+Bh)_c, 4..7 = Bl_c, 8..11 = Al_c.
// ---------------------------------------------------------------------------
#define SG_AH 0
#define SG_AL 32768
#define SG_BH 65536
#define SG_BL 147456
#define SG_TOT 229376

__device__ __forceinline__ uint32_t swz(uint32_t base, int row, int col16) {
    return base + (uint32_t)row * 128 + (uint32_t)((col16 ^ (row & 7)) << 4);
}

#define DO_CHUNK(aBase, bBase)                                                \
    do {                                                                      \
        _Pragma("unroll")                                                     \
        for (int ks = 0; ks < 4; ks++) {                                      \
            uint32_t af[4], bf[10][2];                                        \
            int arow = warp_m * 16 + a_row_l;                                 \
            ldsm4(af[0], af[1], af[2], af[3],                                 \
                  sb + swz((aBase), arow, (ks << 1) | a_c16_l));              \
            _Pragma("unroll")                                                 \
            for (int p = 0; p < 5; p++) {                                     \
                int brow = warp_n * 80 + p * 16 + b_dn_l;                     \
                ldsm4(bf[2*p][0], bf[2*p][1], bf[2*p+1][0], bf[2*p+1][1],     \
                      sb + swz((bBase), brow, (ks << 1) | b_c16_l));          \
            }                                                                 \
            _Pragma("unroll")                                                 \
            for (int nt = 0; nt < 10; nt++)                                   \
                mma16816(acc[nt], af, bf[nt]);                                \
        }                                                                     \
    } while (0)

#define PROGRESSIVE_MAINLOOP(mb0)                                                      \
    MBAR_WAIT((mb0) + 0*8, 0);  DO_CHUNK(SG_AH + 0*8192, SG_BH + 0*20480);             \
    MBAR_WAIT((mb0) + 1*8, 0);  DO_CHUNK(SG_AH + 1*8192, SG_BH + 1*20480);             \
    MBAR_WAIT((mb0) + 2*8, 0);  DO_CHUNK(SG_AH + 2*8192, SG_BH + 2*20480);             \
    MBAR_WAIT((mb0) + 3*8, 0);  DO_CHUNK(SG_AH + 3*8192, SG_BH + 3*20480);             \
    MBAR_WAIT((mb0) + 4*8, 0);  DO_CHUNK(SG_AH + 0*8192, SG_BL + 0*20480);             \
    MBAR_WAIT((mb0) + 5*8, 0);  DO_CHUNK(SG_AH + 1*8192, SG_BL + 1*20480);             \
    MBAR_WAIT((mb0) + 6*8, 0);  DO_CHUNK(SG_AH + 2*8192, SG_BL + 2*20480);             \
    MBAR_WAIT((mb0) + 7*8, 0);  DO_CHUNK(SG_AH + 3*8192, SG_BL + 3*20480);             \
    MBAR_WAIT((mb0) + 8*8, 0);  DO_CHUNK(SG_AL + 0*8192, SG_BH + 0*20480);             \
    MBAR_WAIT((mb0) + 9*8, 0);  DO_CHUNK(SG_AL + 1*8192, SG_BH + 1*20480);             \
    MBAR_WAIT((mb0) + 10*8, 0); DO_CHUNK(SG_AL + 2*8192, SG_BH + 2*20480);             \
    MBAR_WAIT((mb0) + 11*8, 0); DO_CHUNK(SG_AL + 3*8192, SG_BH + 3*20480);

// ---------------------------------------------------------------------------
// s-GEMM + fused split-K reduce + squash.
// grid (4 Mtiles, 36 Ksplits) = 144 CTAs (all co-resident at 1 CTA/SM).
// After writing partials, CTAs with the same bx rendezvous on g_cnt[bx],
// then each reduces its 1/36 of that Mtile's (b,o) groups.
// ---------------------------------------------------------------------------
__global__ void __launch_bounds__(256, 1)
gemm_s(float* __restrict__ out, int t) {
    extern __shared__ char sm[];
    __shared__ __align__(8) uint64_t mbar[12];
    uint32_t sb = smem_to_u32(sm);
    uint32_t mb0 = smem_to_u32(mbar);
    int tid = threadIdx.x, lane = tid & 31, wid = tid >> 5;
    int warp_m = wid & 3, warp_n = wid >> 2;
    int bx = blockIdx.x;                     // mblk
    int by = blockIdx.y;                     // ksplit
    int chunk0 = by * 4;

    if (tid == 0) {
        #pragma unroll
        for (int i = 0; i < 12; i++) MBAR_INIT(mb0 + i * 8, 1);
    }
    __syncthreads();
    if (tid == 0) {
        #pragma unroll
        for (int c = 0; c < 4; c++) {
            uint32_t m = mb0 + c * 8;
            MBAR_EXPECT(m, 8192 + 20480);
            bulkcp(sb + SG_AH + c * 8192,
                   g_A_hi + ((size_t)(chunk0 + c) * 4 + bx) * 8192, 8192, m);
            bulkcp(sb + SG_BH + c * 20480,
                   g_Bt_hi + (size_t)(chunk0 + c) * 20480, 20480, m);
        }
        #pragma unroll
        for (int c = 0; c < 4; c++) {
            uint32_t m = mb0 + (4 + c) * 8;
            MBAR_EXPECT(m, 20480);
            bulkcp(sb + SG_BL + c * 20480,
                   g_Bt_lo + (size_t)(chunk0 + c) * 20480, 20480, m);
        }
        #pragma unroll
        for (int c = 0; c < 4; c++) {
            uint32_t m = mb0 + (8 + c) * 8;
            MBAR_EXPECT(m, 8192);
            bulkcp(sb + SG_AL + c * 8192,
                   g_A_lo + ((size_t)(chunk0 + c) * 4 + bx) * 8192, 8192, m);
        }
    }

    float acc[10][4];
    #pragma unroll
    for (int nt = 0; nt < 10; nt++)
        #pragma unroll
        for (int r = 0; r < 4; r++) acc[nt][r] = 0.f;

    int a_row_l = ((lane >> 3) & 1) * 8 + (lane & 7);
    int a_c16_l = lane >> 4;
    int b_dn_l  = ((lane >> 4) & 1) * 8 + (lane & 7);
    int b_c16_l = (lane >> 3) & 1;

    PROGRESSIVE_MAINLOOP(mb0);

    // Partial tile -> g_part_s[by].
    float* po = g_part_s + (size_t)by * (BATCH * NDIM);
    int r_l = lane >> 2, c_l = (lane & 3) * 2;
    int row = bx * 64 + warp_m * 16 + r_l;
    #pragma unroll
    for (int nt = 0; nt < 10; nt++) {
        int col = warp_n * 80 + nt * 8 + c_l;
        *(float2*)(po + (size_t)row * NDIM + col) = make_float2(acc[nt][0], acc[nt][1]);
        *(float2*)(po + (size_t)(row + 8) * NDIM + col) = make_float2(acc[nt][2], acc[nt][3]);
    }

    // --- rendezvous: wait for all 36 split-CTAs of this Mtile ---
    __threadfence();
    __syncthreads();
    if (tid == 0) {
        atomicAdd(&g_cnt[bx], 1);
        int tgt = SPLITS_S * (t + 1);        // counters are monotonic per call
        while (atomicAdd(&g_cnt[bx], 0) < tgt) __nanosleep(20);
    }
    __syncthreads();

    // --- fused squash: this CTA reduces groups [g0, g0+n) of Mtile bx ---
    // 640 (b,o) groups per Mtile; first 28 split-CTAs take 18, rest 17.
    int n  = (by < 28) ? 18 : 17;
    int g0 = (by < 28) ? by * 18 : 28 * 18 + (by - 28) * 17;
    int u  = tid & 15;
    #pragma unroll
    for (int r = 0; r < 2; r++) {
        int gl = r * 16 + (tid >> 4);
        bool act = gl < n;
        int idx = bx * 10240 + (g0 + gl) * 16 + u;
        float s = 0.f;
        if (act) {
            float a0 = 0.f, a1 = 0.f, a2 = 0.f, a3 = 0.f;
            #pragma unroll
            for (int sp = 0; sp < SPLITS_S; sp += 4) {
                a0 += __ldcg(&g_part_s[(size_t)(sp + 0) * (BATCH * NDIM) + idx]);
                a1 += __ldcg(&g_part_s[(size_t)(sp + 1) * (BATCH * NDIM) + idx]);
                a2 += __ldcg(&g_part_s[(size_t)(sp + 2) * (BATCH * NDIM) + idx]);
                a3 += __ldcg(&g_part_s[(size_t)(sp + 3) * (BATCH * NDIM) + idx]);
            }
            s = (a0 + a1) + (a2 + a3);
        }
        float sq = s * s;
        sq += __shfl_xor_sync(0xffffffffu, sq, 8);
        sq += __shfl_xor_sync(0xffffffffu, sq, 4);
        sq += __shfl_xor_sync(0xffffffffu, sq, 2);
        sq += __shfl_xor_sync(0xffffffffu, sq, 1);
        if (act) {
            float scale = sq / ((1.0f + sq) * sqrtf(sq + 1e-9f));
            float v = s * scale;
            if (t == 2) {
                out[idx] = v;
            } else {
                int b = idx / NDIM;
                int ou = idx - b * NDIM;
                int col = b & 63;            // kc == bx for this region
                uint32_t off = (uint32_t)bx * 20480 + ou * 128
                             + (((col >> 3) ^ (ou & 7)) << 4) + (col & 7) * 2;
                __nv_bfloat16 h, l;
                split_bf16(v, h, l);
                *(unsigned short*)(g_vT2_hi + off) = __bfloat16_as_ushort(h);
                *(unsigned short*)(g_vT2_lo + off) = __bfloat16_as_ushort(l);
            }
        }
    }
}

// ---------------------------------------------------------------------------
// M-GEMM (M[ik,ou] = inpT @ vT^T) + fused b-update + fused Wc build for t+1.
// grid 144, bulk-copy staging + progressive mbarrier waits.
// ---------------------------------------------------------------------------
__global__ void __launch_bounds__(256, 1)
gemm_m(const float* __restrict__ W, int t) {
    extern __shared__ char sm[];
    __shared__ __align__(8) uint64_t mbar[12];
    __shared__ float c_s[8][10];
    uint32_t sb = smem_to_u32(sm);
    uint32_t mb0 = smem_to_u32(mbar);
    int tid = threadIdx.x, lane = tid & 31, wid = tid >> 5;
    int warp_m = wid & 3, warp_n = wid >> 2;
    int cta = blockIdx.x;

    if (tid == 0) {
        #pragma unroll
        for (int i = 0; i < 12; i++) MBAR_INIT(mb0 + i * 8, 1);
    }
    __syncthreads();
    if (tid == 0) {
        #pragma unroll
        for (int c = 0; c < 4; c++) {
            uint32_t m = mb0 + c * 8;
            MBAR_EXPECT(m, 8192 + 20480);
            bulkcp(sb + SG_AH + c * 8192,
                   g_AT_hi + ((size_t)c * NCHUNK + cta) * 8192, 8192, m);
            bulkcp(sb + SG_BH + c * 20480, g_vT2_hi + (size_t)c * 20480, 20480, m);
        }
        #pragma unroll
        for (int c = 0; c < 4; c++) {
            uint32_t m = mb0 + (4 + c) * 8;
            MBAR_EXPECT(m, 20480);
            bulkcp(sb + SG_BL + c * 20480, g_vT2_lo + (size_t)c * 20480, 20480, m);
        }
        #pragma unroll
        for (int c = 0; c < 4; c++) {
            uint32_t m = mb0 + (8 + c) * 8;
            MBAR_EXPECT(m, 8192);
            bulkcp(sb + SG_AL + c * 8192,
                   g_AT_lo + ((size_t)c * NCHUNK + cta) * 8192, 8192, m);
        }
    }

    float acc[10][4];
    #pragma unroll
    for (int nt = 0; nt < 10; nt++)
        #pragma unroll
        for (int r = 0; r < 4; r++) acc[nt][r] = 0.f;

    int a_row_l = ((lane >> 3) & 1) * 8 + (lane & 7);
    int a_c16_l = lane >> 4;
    int b_dn_l  = ((lane >> 4) & 1) * 8 + (lane & 7);
    int b_c16_l = (lane >> 3) & 1;

    PROGRESSIVE_MAINLOOP(mb0);

    // Stage M tile [64][160] fp32 in smem (reuses staging space).
    __syncthreads();
    float* M_s = (float*)sm;
    int r_l = lane >> 2, c_l = (lane & 3) * 2;
    int row = warp_m * 16 + r_l;
    #pragma unroll
    for (int nt = 0; nt < 10; nt++) {
        int col = warp_n * 80 + nt * 8 + c_l;
        *(float2*)(M_s + row * NDIM + col) = make_float2(acc[nt][0], acc[nt][1]);
        *(float2*)(M_s + (row + 8) * NDIM + col) = make_float2(acc[nt][2], acc[nt][3]);
    }
    __syncthreads();

    // b-update: delta[i,o] = (1/B) sum_{k,u} W[i,o,u,k]*M[i8+k][o16+u]
    #pragma unroll
    for (int ee = 0; ee < 10; ee++) {
        int e = wid * 10 + ee;
        int i_rel = e / 10, o = e - i_rel * 10;
        int i = cta * 8 + i_rel;
        float sum = 0.f;
        #pragma unroll
        for (int j = 0; j < 4; j++) {
            int f = lane + (j << 5);
            int k = f >> 4, u = f & 15;
            sum = fmaf(W[(size_t)i * 1280 + (o << 7) + (u << 3) + k],
                       M_s[(i_rel * 8 + k) * NDIM + o * 16 + u], sum);
        }
        #pragma unroll
        for (int off = 16; off; off >>= 1)
            sum += __shfl_xor_sync(0xffffffffu, sum, off);
        if (lane == 0) {
            float d = sum * (1.0f / (float)BATCH);
            int gw = i * OUTCH + o;
            g_b[gw] = (t == 0) ? d : (g_b[gw] + d);
        }
    }
    __syncthreads();

    // Fused Wc build for iteration t+1 (this CTA owns chunk == cta).
    if (tid < 8) {
        int i = cta * 8 + tid;
        float bv[OUTCH], m = -1e30f;
        #pragma unroll
        for (int o = 0; o < OUTCH; o++) {
            bv[o] = g_b[i * OUTCH + o];
            m = fmaxf(m, bv[o]);
        }
        float sum = 0.f;
        #pragma unroll
        for (int o = 0; o < OUTCH; o++) { bv[o] = expf(bv[o] - m); sum += bv[o]; }
        float inv = 1.0f / sum;
        #pragma unroll
        for (int o = 0; o < OUTCH; o++) c_s[tid][o] = bv[o] * inv;
    }
    __syncthreads();
    wc_body(W, cta, c_s, tid);
}

// ---------------------------------------------------------------------------
extern "C" void kernel_launch(void* const* d_in, const int* in_sizes, int n_in,
                              void* d_out, int out_size) {
    const float* inp = (const float*)d_in[0];  // [256,1152,8]
    const float* W   = (const float*)d_in[1];  // [1152,10,16,8]
    float* out = (float*)d_out;                // [256,10,16]

    cudaFuncSetAttribute(gemm_s, cudaFuncAttributeMaxDynamicSharedMemorySize, SG_TOT);
    cudaFuncSetAttribute(gemm_m, cudaFuncAttributeMaxDynamicSharedMemorySize, SG_TOT);

    conv_inp<<<dim3(NCHUNK, 4), 256>>>(inp, W);   // + Wc(0) + counter reset

    for (int t = 0; t < 3; t++) {
        gemm_s<<<dim3(4, SPLITS_S), 256, SG_TOT>>>(out, t);  // + squash
        if (t < 2)
            gemm_m<<<NCHUNK, 256, SG_TOT>>>(W, t);           // + b-update + Wc(t+1)
    }
}

// round 14
// speedup vs baseline: 1.2590x; 1.0851x over previous
#include <cuda_runtime.h>
#include <cuda_bf16.h>
#include <cstdint>

// CapsNet dynamic routing. u_hat never materialized; bf16 hi/lo 3-pass GEMMs
// on mma.sync (m16n8k16, fp32 accum). Pre-swizzled operands + cp.async.bulk
// (per-chunk groups, merged hi/lo passes). 512-thread GEMM CTAs (16 warps).
// squash fused into gemm_s via per-Mtile arrival counters; Wc(t+1) fused into
// gemm_m(t); Wc(0) fused into conv_inp. 6 launches total.
//   inp: [256,1152,8] fp32, W: [1152,10,16,8] fp32, out v: [256,10,16] fp32
//
// All __device__ globals referenced only inside device code (host-passed
// __device__ symbols silently resolve to ATS host memory on GB300).

#define BATCH   256
#define INCH    1152
#define INU     8
#define OUTCH   10
#define OUTU    16
#define KDIM    (INCH*INU)     // 9216
#define NDIM    (OUTCH*OUTU)   // 160
#define NCHUNK  144            // 64-k chunks (8 capsules each)
#define SPLITS_S 36            // s-GEMM K splits (4 chunks = 256 K per CTA)

// ---------------- device globals (pre-swizzled tile storage) ---------------
__device__ __align__(16) unsigned char g_A_hi[NCHUNK * 4 * 8192];   // [chunk][mblk][64x128B]
__device__ __align__(16) unsigned char g_A_lo[NCHUNK * 4 * 8192];
__device__ __align__(16) unsigned char g_AT_hi[4 * NCHUNK * 8192];  // [kc][ikblk][64x128B]
__device__ __align__(16) unsigned char g_AT_lo[4 * NCHUNK * 8192];
__device__ __align__(16) unsigned char g_Bt_hi[NCHUNK * 20480];     // [chunk][160x128B]
__device__ __align__(16) unsigned char g_Bt_lo[NCHUNK * 20480];
__device__ __align__(16) unsigned char g_vT2_hi[4 * 20480];         // [kc][160x128B]
__device__ __align__(16) unsigned char g_vT2_lo[4 * 20480];
__device__ float g_part_s[SPLITS_S * BATCH * NDIM];                 // 5.9 MB
__device__ float g_b[INCH * OUTCH];
__device__ int   g_cnt[4];                                          // per-Mtile arrivals

__device__ __forceinline__ uint32_t smem_to_u32(const void* p) {
    uint32_t a;
    asm("{ .reg .u64 t; cvta.to.shared.u64 t, %1; cvt.u32.u64 %0, t; }"
        : "=r"(a) : "l"(p));
    return a;
}
__device__ __forceinline__ void split_bf16(float x, __nv_bfloat16& h, __nv_bfloat16& l) {
    h = __float2bfloat16(x);
    l = __float2bfloat16(x - __bfloat162float(h));
}
__device__ __forceinline__ void ldsm4(uint32_t& r0, uint32_t& r1, uint32_t& r2,
                                      uint32_t& r3, uint32_t addr) {
    asm volatile("ldmatrix.sync.aligned.m8n8.x4.shared.b16 {%0,%1,%2,%3}, [%4];"
                 : "=r"(r0), "=r"(r1), "=r"(r2), "=r"(r3) : "r"(addr));
}
__device__ __forceinline__ void ldsm2(uint32_t& r0, uint32_t& r1, uint32_t addr) {
    asm volatile("ldmatrix.sync.aligned.m8n8.x2.shared.b16 {%0,%1}, [%2];"
                 : "=r"(r0), "=r"(r1) : "r"(addr));
}
__device__ __forceinline__ void mma16816(float* d, const uint32_t* a,
                                         const uint32_t* b) {
    asm volatile(
        "mma.sync.aligned.m16n8k16.row.col.f32.bf16.bf16.f32 "
        "{%0,%1,%2,%3}, {%4,%5,%6,%7}, {%8,%9}, {%0,%1,%2,%3};"
        : "+f"(d[0]), "+f"(d[1]), "+f"(d[2]), "+f"(d[3])
        : "r"(a[0]), "r"(a[1]), "r"(a[2]), "r"(a[3]), "r"(b[0]), "r"(b[1]));
}

// ---- mbarrier + bulk-copy primitives (sm_90 baseline PTX) ----
#define MBAR_INIT(a, c) \
    asm volatile("mbarrier.init.shared.b64 [%0], %1;" \
                 :: "r"((uint32_t)(a)), "r"((uint32_t)(c)) : "memory")
#define MBAR_EXPECT(a, tx) \
    asm volatile("mbarrier.arrive.expect_tx.shared.b64 _, [%0], %1;" \
                 :: "r"((uint32_t)(a)), "r"((uint32_t)(tx)) : "memory")
#define MBAR_WAIT(a, ph) do { \
    uint32_t _mb = (uint32_t)(a); uint32_t _p = (uint32_t)(ph); uint32_t _d; \
    asm volatile("{\n\t.reg .pred p;\n\t" \
        "mbarrier.try_wait.parity.acquire.cta.shared::cta.b64 p, [%1], %2;\n\t" \
        "selp.b32 %0, 1, 0, p;\n\t}" : "=r"(_d) : "r"(_mb), "r"(_p) : "memory"); \
    if (!_d) { \
        asm volatile("{\n\t.reg .pred P1;\n\tWL_%=:\n\t" \
            "mbarrier.try_wait.parity.acquire.cta.shared::cta.b64 P1, [%0], %1, 0x989680;\n\t" \
            "@P1 bra.uni WD_%=;\n\tbra.uni WL_%=;\n\tWD_%=:\n\t}" \
            :: "r"(_mb), "r"(_p) : "memory"); \
    } } while (0)
__device__ __forceinline__ void bulkcp(uint32_t dst, const void* src,
                                       uint32_t bytes, uint32_t mbar) {
    asm volatile(
        "cp.async.bulk.shared::cluster.global.mbarrier::complete_tx::bytes "
        "[%0], [%1], %2, [%3];"
        :: "r"(dst), "l"(src), "r"(bytes), "r"(mbar) : "memory");
}

// ---------------------------------------------------------------------------
// Wc body: g_Bt[chunk] (pre-swizzled 160x128B) = c[i,o]*W[i,o,u,k] hi/lo.
// ---------------------------------------------------------------------------
template <int NT>
__device__ __forceinline__ void wc_body(const float* __restrict__ W, int chunk,
                                        const float (*c_s)[10], int tid) {
    const float4* W4 = (const float4*)(W + (size_t)chunk * 8 * 1280);
    unsigned char* bh = g_Bt_hi + (size_t)chunk * 20480;
    unsigned char* bl = g_Bt_lo + (size_t)chunk * 20480;
    #pragma unroll
    for (int r = 0; r < 2560 / NT; r++) {
        int q = tid + r * NT;                // 0..2559 float4s (8 caps x 320)
        int i_off = q / 320;
        int rem = q - i_off * 320;
        int o = rem >> 5;
        int rem2 = rem & 31;
        int u = rem2 >> 1, kh = rem2 & 1;
        float4 f = W4[q];
        float cv = c_s[i_off][o];
        __nv_bfloat16 h0,l0,h1,l1,h2,l2,h3,l3;
        split_bf16(f.x * cv, h0, l0);
        split_bf16(f.y * cv, h1, l1);
        split_bf16(f.z * cv, h2, l2);
        split_bf16(f.w * cv, h3, l3);
        uint2 ph, pl;
        ph.x = (uint32_t)__bfloat16_as_ushort(h0) | ((uint32_t)__bfloat16_as_ushort(h1) << 16);
        ph.y = (uint32_t)__bfloat16_as_ushort(h2) | ((uint32_t)__bfloat16_as_ushort(h3) << 16);
        pl.x = (uint32_t)__bfloat16_as_ushort(l0) | ((uint32_t)__bfloat16_as_ushort(l1) << 16);
        pl.y = (uint32_t)__bfloat16_as_ushort(l2) | ((uint32_t)__bfloat16_as_ushort(l3) << 16);
        int row = o * 16 + u;
        uint32_t off = (uint32_t)row * 128 + ((i_off ^ (row & 7)) << 4) + kh * 8;
        *(uint2*)(bh + off) = ph;
        *(uint2*)(bl + off) = pl;
    }
}

// ---------------------------------------------------------------------------
// One-time: inp -> bf16 hi/lo pre-swizzled tiles (both layouts); fused Wc(0)
// for by==0 blocks; resets g_cnt. grid (144, 4), 256 threads.
// ---------------------------------------------------------------------------
__global__ void conv_inp(const float* __restrict__ inp, const float* __restrict__ W) {
    __shared__ unsigned short sh_hi[64][72];
    __shared__ unsigned short sh_lo[64][72];
    __shared__ float c_s[8][10];
    int ik0 = blockIdx.x * 64, b0 = blockIdx.y * 64;
    int tid = threadIdx.x;

    if (blockIdx.x == 0 && blockIdx.y == 0 && tid < 4) g_cnt[tid] = 0;

    #pragma unroll
    for (int it = 0; it < 16; it++) {
        int row = it * 4 + (tid >> 6);     // b within tile
        int col = tid & 63;                // ik within tile
        float x = inp[(size_t)(b0 + row) * KDIM + ik0 + col];
        __nv_bfloat16 h, l;
        split_bf16(x, h, l);
        sh_hi[row][col] = __bfloat16_as_ushort(h);
        sh_lo[row][col] = __bfloat16_as_ushort(l);
    }
    __syncthreads();

    unsigned char* Ah = g_A_hi + ((size_t)blockIdx.x * 4 + blockIdx.y) * 8192;
    unsigned char* Al = g_A_lo + ((size_t)blockIdx.x * 4 + blockIdx.y) * 8192;
    unsigned char* Th = g_AT_hi + ((size_t)blockIdx.y * NCHUNK + blockIdx.x) * 8192;
    unsigned char* Tl = g_AT_lo + ((size_t)blockIdx.y * NCHUNK + blockIdx.x) * 8192;

    #pragma unroll
    for (int k = 0; k < 4; k++) {
        int w = tid + (k << 8);            // 0..1023 uint2 slots
        int r = w >> 4, g = w & 15;
        uint32_t off = (uint32_t)r * 128 + ((((g >> 1) ^ (r & 7))) << 4) + (g & 1) * 8;
        {
            int c0 = g * 4;
            uint2 vh, vl;
            vh.x = (uint32_t)sh_hi[r][c0] | ((uint32_t)sh_hi[r][c0+1] << 16);
            vh.y = (uint32_t)sh_hi[r][c0+2] | ((uint32_t)sh_hi[r][c0+3] << 16);
            vl.x = (uint32_t)sh_lo[r][c0] | ((uint32_t)sh_lo[r][c0+1] << 16);
            vl.y = (uint32_t)sh_lo[r][c0+2] | ((uint32_t)sh_lo[r][c0+3] << 16);
            *(uint2*)(Ah + off) = vh;
            *(uint2*)(Al + off) = vl;
        }
        {
            int c0 = g * 4;
            uint2 vh, vl;
            vh.x = (uint32_t)sh_hi[c0][r] | ((uint32_t)sh_hi[c0+1][r] << 16);
            vh.y = (uint32_t)sh_hi[c0+2][r] | ((uint32_t)sh_hi[c0+3][r] << 16);
            vl.x = (uint32_t)sh_lo[c0][r] | ((uint32_t)sh_lo[c0+1][r] << 16);
            vl.y = (uint32_t)sh_lo[c0+2][r] | ((uint32_t)sh_lo[c0+3][r] << 16);
            *(uint2*)(Th + off) = vh;
            *(uint2*)(Tl + off) = vl;
        }
    }

    if (blockIdx.y == 0) {
        if (tid < 80) c_s[tid / 10][tid % 10] = 0.1f;
        __syncthreads();
        wc_body<256>(W, blockIdx.x, c_s, tid);
    }
}

// ---------------------------------------------------------------------------
// Per-chunk staging layout (4 x 56 KB = 224 KB):
//   chunk c at c*57344:  AH @0 (8192) | AL @8192 | BH @16384 (20480) | BL @36864
// 4 mbarriers, one per chunk (expect 57344 bytes each).
// GEMM geometry: 512 thr, 16 warps (4M x 4N), warp tile 16x40, acc 20 regs.
// Merged passes: per ks load af_h/af_l (ldsm4) + bf_h/bf_l (ldsm2 x5) once,
// issue 15 MMAs (AhBh + AhBl + AlBh).
// ---------------------------------------------------------------------------
#define CHB 57344
#define SG_TOT (4*CHB)      // 229376

__device__ __forceinline__ uint32_t swz(uint32_t base, int row, int col16) {
    return base + (uint32_t)row * 128 + (uint32_t)((col16 ^ (row & 7)) << 4);
}

#define GEMM_MAINLOOP(mb0)                                                     \
    _Pragma("unroll")                                                          \
    for (int c = 0; c < 4; c++) {                                              \
        MBAR_WAIT((mb0) + c * 8, 0);                                           \
        uint32_t cb = sb + c * CHB;                                            \
        _Pragma("unroll")                                                      \
        for (int ks = 0; ks < 4; ks++) {                                       \
            uint32_t ah[4], al[4], bh[5][2], bl[5][2];                         \
            int arow = warp_m * 16 + a_row_l;                                  \
            int ac = (ks << 1) | a_c16_l;                                      \
            ldsm4(ah[0], ah[1], ah[2], ah[3], swz(cb + 0, arow, ac));          \
            ldsm4(al[0], al[1], al[2], al[3], swz(cb + 8192, arow, ac));       \
            int bc = (ks << 1) | b_c16_l;                                      \
            _Pragma("unroll")                                                  \
            for (int p = 0; p < 5; p++) {                                      \
                int brow = warp_n * 40 + p * 8 + b_row_l;                      \
                ldsm2(bh[p][0], bh[p][1], swz(cb + 16384, brow, bc));          \
                ldsm2(bl[p][0], bl[p][1], swz(cb + 36864, brow, bc));          \
            }                                                                  \
            _Pragma("unroll")                                                  \
            for (int p = 0; p < 5; p++) {                                      \
                mma16816(acc[p], ah, bh[p]);                                   \
                mma16816(acc[p], ah, bl[p]);                                   \
                mma16816(acc[p], al, bh[p]);                                   \
            }                                                                  \
        }                                                                      \
    }

// ---------------------------------------------------------------------------
// s-GEMM + fused split-K reduce + squash.
// grid (4 Mtiles, 36 Ksplits) = 144 CTAs (co-resident, 1 CTA/SM).
// ---------------------------------------------------------------------------
__global__ void __launch_bounds__(512, 1)
gemm_s(float* __restrict__ out, int t) {
    extern __shared__ char sm[];
    __shared__ __align__(8) uint64_t mbar[4];
    uint32_t sb = smem_to_u32(sm);
    uint32_t mb0 = smem_to_u32(mbar);
    int tid = threadIdx.x, lane = tid & 31, wid = tid >> 5;
    int warp_m = wid & 3, warp_n = wid >> 2;      // 4M x 4N
    int bx = blockIdx.x;                          // mblk
    int by = blockIdx.y;                          // ksplit
    int chunk0 = by * 4;

    if (tid == 0) {
        #pragma unroll
        for (int i = 0; i < 4; i++) MBAR_INIT(mb0 + i * 8, 1);
    }
    __syncthreads();
    if (tid == 0) {
        #pragma unroll
        for (int c = 0; c < 4; c++) {
            uint32_t m = mb0 + c * 8;
            uint32_t cb = sb + c * CHB;
            int ch = chunk0 + c;
            MBAR_EXPECT(m, CHB);
            bulkcp(cb + 0,     g_A_hi + ((size_t)ch * 4 + bx) * 8192, 8192, m);
            bulkcp(cb + 8192,  g_A_lo + ((size_t)ch * 4 + bx) * 8192, 8192, m);
            bulkcp(cb + 16384, g_Bt_hi + (size_t)ch * 20480, 20480, m);
            bulkcp(cb + 36864, g_Bt_lo + (size_t)ch * 20480, 20480, m);
        }
    }

    float acc[5][4];
    #pragma unroll
    for (int p = 0; p < 5; p++)
        #pragma unroll
        for (int r = 0; r < 4; r++) acc[p][r] = 0.f;

    int a_row_l = ((lane >> 3) & 1) * 8 + (lane & 7);
    int a_c16_l = lane >> 4;
    int b_row_l = lane & 7;
    int b_c16_l = (lane >> 3) & 1;

    GEMM_MAINLOOP(mb0);

    // Partial tile -> g_part_s[by].
    float* po = g_part_s + (size_t)by * (BATCH * NDIM);
    int r_l = lane >> 2, c_l = (lane & 3) * 2;
    int row = bx * 64 + warp_m * 16 + r_l;
    #pragma unroll
    for (int p = 0; p < 5; p++) {
        int col = warp_n * 40 + p * 8 + c_l;
        *(float2*)(po + (size_t)row * NDIM + col) = make_float2(acc[p][0], acc[p][1]);
        *(float2*)(po + (size_t)(row + 8) * NDIM + col) = make_float2(acc[p][2], acc[p][3]);
    }

    // --- rendezvous: wait for all 36 split-CTAs of this Mtile ---
    __threadfence();
    __syncthreads();
    if (tid == 0) {
        atomicAdd(&g_cnt[bx], 1);
        int tgt = SPLITS_S * (t + 1);        // counters monotonic per call
        while (atomicAdd(&g_cnt[bx], 0) < tgt) __nanosleep(20);
    }
    __syncthreads();

    // --- fused squash: reduce groups [g0, g0+n) of Mtile bx ---
    // 640 (b,o) groups per Mtile; first 28 split-CTAs take 18, rest 17.
    int n  = (by < 28) ? 18 : 17;
    int g0 = (by < 28) ? by * 18 : 28 * 18 + (by - 28) * 17;
    int gl = tid >> 4;                        // 0..31
    int u  = tid & 15;
    bool act = gl < n;
    int idx = bx * 10240 + (g0 + gl) * 16 + u;
    float s = 0.f;
    if (act) {
        float a0 = 0.f, a1 = 0.f, a2 = 0.f, a3 = 0.f;
        #pragma unroll
        for (int sp = 0; sp < SPLITS_S; sp += 4) {
            a0 += __ldcg(&g_part_s[(size_t)(sp + 0) * (BATCH * NDIM) + idx]);
            a1 += __ldcg(&g_part_s[(size_t)(sp + 1) * (BATCH * NDIM) + idx]);
            a2 += __ldcg(&g_part_s[(size_t)(sp + 2) * (BATCH * NDIM) + idx]);
            a3 += __ldcg(&g_part_s[(size_t)(sp + 3) * (BATCH * NDIM) + idx]);
        }
        s = (a0 + a1) + (a2 + a3);
    }
    float sq = s * s;
    sq += __shfl_xor_sync(0xffffffffu, sq, 8);
    sq += __shfl_xor_sync(0xffffffffu, sq, 4);
    sq += __shfl_xor_sync(0xffffffffu, sq, 2);
    sq += __shfl_xor_sync(0xffffffffu, sq, 1);
    if (act) {
        float scale = sq / ((1.0f + sq) * sqrtf(sq + 1e-9f));
        float v = s * scale;
        if (t == 2) {
            out[idx] = v;
        } else {
            int b = idx / NDIM;
            int ou = idx - b * NDIM;
            int col = b & 63;                 // kc == bx for this region
            uint32_t off = (uint32_t)bx * 20480 + ou * 128
                         + (((col >> 3) ^ (ou & 7)) << 4) + (col & 7) * 2;
            __nv_bfloat16 h, l;
            split_bf16(v, h, l);
            *(unsigned short*)(g_vT2_hi + off) = __bfloat16_as_ushort(h);
            *(unsigned short*)(g_vT2_lo + off) = __bfloat16_as_ushort(l);
        }
    }
}

// ---------------------------------------------------------------------------
// M-GEMM (M[ik,ou] = inpT @ vT^T) + fused b-update + fused Wc build for t+1.
// grid 144, per-chunk bulk staging, 512 threads.
// ---------------------------------------------------------------------------
__global__ void __launch_bounds__(512, 1)
gemm_m(const float* __restrict__ W, int t) {
    extern __shared__ char sm[];
    __shared__ __align__(8) uint64_t mbar[4];
    __shared__ float c_s[8][10];
    uint32_t sb = smem_to_u32(sm);
    uint32_t mb0 = smem_to_u32(mbar);
    int tid = threadIdx.x, lane = tid & 31, wid = tid >> 5;
    int warp_m = wid & 3, warp_n = wid >> 2;
    int cta = blockIdx.x;

    if (tid == 0) {
        #pragma unroll
        for (int i = 0; i < 4; i++) MBAR_INIT(mb0 + i * 8, 1);
    }
    __syncthreads();
    if (tid == 0) {
        #pragma unroll
        for (int c = 0; c < 4; c++) {
            uint32_t m = mb0 + c * 8;
            uint32_t cb = sb + c * CHB;
            MBAR_EXPECT(m, CHB);
            bulkcp(cb + 0,     g_AT_hi + ((size_t)c * NCHUNK + cta) * 8192, 8192, m);
            bulkcp(cb + 8192,  g_AT_lo + ((size_t)c * NCHUNK + cta) * 8192, 8192, m);
            bulkcp(cb + 16384, g_vT2_hi + (size_t)c * 20480, 20480, m);
            bulkcp(cb + 36864, g_vT2_lo + (size_t)c * 20480, 20480, m);
        }
    }

    float acc[5][4];
    #pragma unroll
    for (int p = 0; p < 5; p++)
        #pragma unroll
        for (int r = 0; r < 4; r++) acc[p][r] = 0.f;

    int a_row_l = ((lane >> 3) & 1) * 8 + (lane & 7);
    int a_c16_l = lane >> 4;
    int b_row_l = lane & 7;
    int b_c16_l = (lane >> 3) & 1;

    GEMM_MAINLOOP(mb0);

    // Stage M tile [64][160] fp32 in smem (reuses staging space).
    __syncthreads();
    float* M_s = (float*)sm;
    int r_l = lane >> 2, c_l = (lane & 3) * 2;
    int row = warp_m * 16 + r_l;
    #pragma unroll
    for (int p = 0; p < 5; p++) {
        int col = warp_n * 40 + p * 8 + c_l;
        *(float2*)(M_s + row * NDIM + col) = make_float2(acc[p][0], acc[p][1]);
        *(float2*)(M_s + (row + 8) * NDIM + col) = make_float2(acc[p][2], acc[p][3]);
    }
    __syncthreads();

    // b-update: delta[i,o] = (1/B) sum_{k,u} W[i,o,u,k]*M[i8+k][o16+u]
    // 80 outputs per CTA (8 capsules x 10), 5 per warp.
    #pragma unroll
    for (int ee = 0; ee < 5; ee++) {
        int e = wid * 5 + ee;
        int i_rel = e / 10, o = e - i_rel * 10;
        int i = cta * 8 + i_rel;
        float sum = 0.f;
        #pragma unroll
        for (int j = 0; j < 4; j++) {
            int f = lane + (j << 5);
            int k = f >> 4, u = f & 15;
            sum = fmaf(W[(size_t)i * 1280 + (o << 7) + (u << 3) + k],
                       M_s[(i_rel * 8 + k) * NDIM + o * 16 + u], sum);
        }
        #pragma unroll
        for (int off = 16; off; off >>= 1)
            sum += __shfl_xor_sync(0xffffffffu, sum, off);
        if (lane == 0) {
            float d = sum * (1.0f / (float)BATCH);
            int gw = i * OUTCH + o;
            g_b[gw] = (t == 0) ? d : (g_b[gw] + d);
        }
    }
    __syncthreads();

    // Fused Wc build for iteration t+1 (this CTA owns chunk == cta).
    if (tid < 8) {
        int i = cta * 8 + tid;
        float bv[OUTCH], m = -1e30f;
        #pragma unroll
        for (int o = 0; o < OUTCH; o++) {
            bv[o] = g_b[i * OUTCH + o];
            m = fmaxf(m, bv[o]);
        }
        float sum = 0.f;
        #pragma unroll
        for (int o = 0; o < OUTCH; o++) { bv[o] = expf(bv[o] - m); sum += bv[o]; }
        float inv = 1.0f / sum;
        #pragma unroll
        for (int o = 0; o < OUTCH; o++) c_s[tid][o] = bv[o] * inv;
    }
    __syncthreads();
    wc_body<512>(W, cta, c_s, tid);
}

// ---------------------------------------------------------------------------
extern "C" void kernel_launch(void* const* d_in, const int* in_sizes, int n_in,
                              void* d_out, int out_size) {
    const float* inp = (const float*)d_in[0];  // [256,1152,8]
    const float* W   = (const float*)d_in[1];  // [1152,10,16,8]
    float* out = (float*)d_out;                // [256,10,16]

    cudaFuncSetAttribute(gemm_s, cudaFuncAttributeMaxDynamicSharedMemorySize, SG_TOT);
    cudaFuncSetAttribute(gemm_m, cudaFuncAttributeMaxDynamicSharedMemorySize, SG_TOT);

    conv_inp<<<dim3(NCHUNK, 4), 256>>>(inp, W);   // + Wc(0) + counter reset

    for (int t = 0; t < 3; t++) {
        gemm_s<<<dim3(4, SPLITS_S), 512, SG_TOT>>>(out, t);  // + squash
        if (t < 2)
            gemm_m<<<NCHUNK, 512, SG_TOT>>>(W, t);           // + b-update + Wc(t+1)
    }
}

// round 15
// speedup vs baseline: 1.2725x; 1.0108x over previous
#include <cuda_runtime.h>
#include <cuda_bf16.h>
#include <cstdint>

// CapsNet dynamic routing. u_hat never materialized; bf16 hi/lo 3-pass GEMMs
// on mma.sync (m16n8k16, fp32 accum). Pre-swizzled operands + cp.async.bulk.
// 512-thread GEMM CTAs (16 warps, merged hi/lo passes).
// Launches (4): conv+Wc(0) | gemm_s(0)+squash | fused(1) | fused(2)
// fused(t) = [M-GEMM(t-1) + b-update + Wc(t)] --chunk flags--> [s-GEMM(t)+squash]
//   inp: [256,1152,8] fp32, W: [1152,10,16,8] fp32, out v: [256,10,16] fp32
//
// All __device__ globals referenced only inside device code (host-passed
// __device__ symbols silently resolve to ATS host memory on GB300).

#define BATCH   256
#define INCH    1152
#define INU     8
#define OUTCH   10
#define OUTU    16
#define KDIM    (INCH*INU)     // 9216
#define NDIM    (OUTCH*OUTU)   // 160
#define NCHUNK  144            // 64-k chunks (8 capsules each)
#define SPLITS_S 36            // s-GEMM K splits (4 chunks = 256 K per CTA)

// ---------------- device globals (pre-swizzled tile storage) ---------------
__device__ __align__(16) unsigned char g_A_hi[NCHUNK * 4 * 8192];   // [chunk][mblk][64x128B]
__device__ __align__(16) unsigned char g_A_lo[NCHUNK * 4 * 8192];
__device__ __align__(16) unsigned char g_AT_hi[4 * NCHUNK * 8192];  // [kc][ikblk][64x128B]
__device__ __align__(16) unsigned char g_AT_lo[4 * NCHUNK * 8192];
__device__ __align__(16) unsigned char g_Bt_hi[NCHUNK * 20480];     // [chunk][160x128B]
__device__ __align__(16) unsigned char g_Bt_lo[NCHUNK * 20480];
__device__ __align__(16) unsigned char g_vT2_hi[4 * 20480];         // [kc][160x128B]
__device__ __align__(16) unsigned char g_vT2_lo[4 * 20480];
__device__ float g_part_s[SPLITS_S * BATCH * NDIM];                 // 5.9 MB
__device__ float g_b[INCH * OUTCH];
__device__ int   g_cnt[4];                                          // per-Mtile arrivals
__device__ int   g_flag[NCHUNK];                                    // Bt chunk ready

__device__ __forceinline__ uint32_t smem_to_u32(const void* p) {
    uint32_t a;
    asm("{ .reg .u64 t; cvta.to.shared.u64 t, %1; cvt.u32.u64 %0, t; }"
        : "=r"(a) : "l"(p));
    return a;
}
__device__ __forceinline__ void split_bf16(float x, __nv_bfloat16& h, __nv_bfloat16& l) {
    h = __float2bfloat16(x);
    l = __float2bfloat16(x - __bfloat162float(h));
}
__device__ __forceinline__ void ldsm4(uint32_t& r0, uint32_t& r1, uint32_t& r2,
                                      uint32_t& r3, uint32_t addr) {
    asm volatile("ldmatrix.sync.aligned.m8n8.x4.shared.b16 {%0,%1,%2,%3}, [%4];"
                 : "=r"(r0), "=r"(r1), "=r"(r2), "=r"(r3) : "r"(addr));
}
__device__ __forceinline__ void ldsm2(uint32_t& r0, uint32_t& r1, uint32_t addr) {
    asm volatile("ldmatrix.sync.aligned.m8n8.x2.shared.b16 {%0,%1}, [%2];"
                 : "=r"(r0), "=r"(r1) : "r"(addr));
}
__device__ __forceinline__ void mma16816(float* d, const uint32_t* a,
                                         const uint32_t* b) {
    asm volatile(
        "mma.sync.aligned.m16n8k16.row.col.f32.bf16.bf16.f32 "
        "{%0,%1,%2,%3}, {%4,%5,%6,%7}, {%8,%9}, {%0,%1,%2,%3};"
        : "+f"(d[0]), "+f"(d[1]), "+f"(d[2]), "+f"(d[3])
        : "r"(a[0]), "r"(a[1]), "r"(a[2]), "r"(a[3]), "r"(b[0]), "r"(b[1]));
}

// ---- mbarrier + bulk-copy primitives (sm_90 baseline PTX) ----
#define MBAR_INIT(a, c) \
    asm volatile("mbarrier.init.shared.b64 [%0], %1;" \
                 :: "r"((uint32_t)(a)), "r"((uint32_t)(c)) : "memory")
#define MBAR_EXPECT(a, tx) \
    asm volatile("mbarrier.arrive.expect_tx.shared.b64 _, [%0], %1;" \
                 :: "r"((uint32_t)(a)), "r"((uint32_t)(tx)) : "memory")
#define MBAR_WAIT(a, ph) do { \
    uint32_t _mb = (uint32_t)(a); uint32_t _p = (uint32_t)(ph); uint32_t _d; \
    asm volatile("{\n\t.reg .pred p;\n\t" \
        "mbarrier.try_wait.parity.acquire.cta.shared::cta.b64 p, [%1], %2;\n\t" \
        "selp.b32 %0, 1, 0, p;\n\t}" : "=r"(_d) : "r"(_mb), "r"(_p) : "memory"); \
    if (!_d) { \
        asm volatile("{\n\t.reg .pred P1;\n\tWL_%=:\n\t" \
            "mbarrier.try_wait.parity.acquire.cta.shared::cta.b64 P1, [%0], %1, 0x989680;\n\t" \
            "@P1 bra.uni WD_%=;\n\tbra.uni WL_%=;\n\tWD_%=:\n\t}" \
            :: "r"(_mb), "r"(_p) : "memory"); \
    } } while (0)
__device__ __forceinline__ void bulkcp(uint32_t dst, const void* src,
                                       uint32_t bytes, uint32_t mbar) {
    asm volatile(
        "cp.async.bulk.shared::cluster.global.mbarrier::complete_tx::bytes "
        "[%0], [%1], %2, [%3];"
        :: "r"(dst), "l"(src), "r"(bytes), "r"(mbar) : "memory");
}

// ---------------------------------------------------------------------------
// Wc body: g_Bt[chunk] (pre-swizzled 160x128B) = c[i,o]*W[i,o,u,k] hi/lo.
// ---------------------------------------------------------------------------
template <int NT>
__device__ __forceinline__ void wc_body(const float* __restrict__ W, int chunk,
                                        const float (*c_s)[10], int tid) {
    const float4* W4 = (const float4*)(W + (size_t)chunk * 8 * 1280);
    unsigned char* bh = g_Bt_hi + (size_t)chunk * 20480;
    unsigned char* bl = g_Bt_lo + (size_t)chunk * 20480;
    #pragma unroll
    for (int r = 0; r < 2560 / NT; r++) {
        int q = tid + r * NT;                // 0..2559 float4s (8 caps x 320)
        int i_off = q / 320;
        int rem = q - i_off * 320;
        int o = rem >> 5;
        int rem2 = rem & 31;
        int u = rem2 >> 1, kh = rem2 & 1;
        float4 f = W4[q];
        float cv = c_s[i_off][o];
        __nv_bfloat16 h0,l0,h1,l1,h2,l2,h3,l3;
        split_bf16(f.x * cv, h0, l0);
        split_bf16(f.y * cv, h1, l1);
        split_bf16(f.z * cv, h2, l2);
        split_bf16(f.w * cv, h3, l3);
        uint2 ph, pl;
        ph.x = (uint32_t)__bfloat16_as_ushort(h0) | ((uint32_t)__bfloat16_as_ushort(h1) << 16);
        ph.y = (uint32_t)__bfloat16_as_ushort(h2) | ((uint32_t)__bfloat16_as_ushort(h3) << 16);
        pl.x = (uint32_t)__bfloat16_as_ushort(l0) | ((uint32_t)__bfloat16_as_ushort(l1) << 16);
        pl.y = (uint32_t)__bfloat16_as_ushort(l2) | ((uint32_t)__bfloat16_as_ushort(l3) << 16);
        int row = o * 16 + u;
        uint32_t off = (uint32_t)row * 128 + ((i_off ^ (row & 7)) << 4) + kh * 8;
        *(uint2*)(bh + off) = ph;
        *(uint2*)(bl + off) = pl;
    }
}

// ---------------------------------------------------------------------------
// One-time: inp -> bf16 hi/lo pre-swizzled tiles (both layouts); fused Wc(0);
// resets g_cnt and g_flag. grid (144, 4), 256 threads.
// ---------------------------------------------------------------------------
__global__ void conv_inp(const float* __restrict__ inp, const float* __restrict__ W) {
    __shared__ unsigned short sh_hi[64][72];
    __shared__ unsigned short sh_lo[64][72];
    __shared__ float c_s[8][10];
    int ik0 = blockIdx.x * 64, b0 = blockIdx.y * 64;
    int tid = threadIdx.x;

    if (blockIdx.y == 1 && tid == 0) g_flag[blockIdx.x] = 0;
    if (blockIdx.x == 0 && blockIdx.y == 0 && tid < 4) g_cnt[tid] = 0;

    #pragma unroll
    for (int it = 0; it < 16; it++) {
        int row = it * 4 + (tid >> 6);
        int col = tid & 63;
        float x = inp[(size_t)(b0 + row) * KDIM + ik0 + col];
        __nv_bfloat16 h, l;
        split_bf16(x, h, l);
        sh_hi[row][col] = __bfloat16_as_ushort(h);
        sh_lo[row][col] = __bfloat16_as_ushort(l);
    }
    __syncthreads();

    unsigned char* Ah = g_A_hi + ((size_t)blockIdx.x * 4 + blockIdx.y) * 8192;
    unsigned char* Al = g_A_lo + ((size_t)blockIdx.x * 4 + blockIdx.y) * 8192;
    unsigned char* Th = g_AT_hi + ((size_t)blockIdx.y * NCHUNK + blockIdx.x) * 8192;
    unsigned char* Tl = g_AT_lo + ((size_t)blockIdx.y * NCHUNK + blockIdx.x) * 8192;

    #pragma unroll
    for (int k = 0; k < 4; k++) {
        int w = tid + (k << 8);
        int r = w >> 4, g = w & 15;
        uint32_t off = (uint32_t)r * 128 + ((((g >> 1) ^ (r & 7))) << 4) + (g & 1) * 8;
        {
            int c0 = g * 4;
            uint2 vh, vl;
            vh.x = (uint32_t)sh_hi[r][c0] | ((uint32_t)sh_hi[r][c0+1] << 16);
            vh.y = (uint32_t)sh_hi[r][c0+2] | ((uint32_t)sh_hi[r][c0+3] << 16);
            vl.x = (uint32_t)sh_lo[r][c0] | ((uint32_t)sh_lo[r][c0+1] << 16);
            vl.y = (uint32_t)sh_lo[r][c0+2] | ((uint32_t)sh_lo[r][c0+3] << 16);
            *(uint2*)(Ah + off) = vh;
            *(uint2*)(Al + off) = vl;
        }
        {
            int c0 = g * 4;
            uint2 vh, vl;
            vh.x = (uint32_t)sh_hi[c0][r] | ((uint32_t)sh_hi[c0+1][r] << 16);
            vh.y = (uint32_t)sh_hi[c0+2][r] | ((uint32_t)sh_hi[c0+3][r] << 16);
            vl.x = (uint32_t)sh_lo[c0][r] | ((uint32_t)sh_lo[c0+1][r] << 16);
            vl.y = (uint32_t)sh_lo[c0+2][r] | ((uint32_t)sh_lo[c0+3][r] << 16);
            *(uint2*)(Th + off) = vh;
            *(uint2*)(Tl + off) = vl;
        }
    }

    if (blockIdx.y == 0) {
        if (tid < 80) c_s[tid / 10][tid % 10] = 0.1f;
        __syncthreads();
        wc_body<256>(W, blockIdx.x, c_s, tid);
    }
}

// ---------------------------------------------------------------------------
// Per-chunk staging (4 x 56 KB): chunk c at c*57344:
//   AH @0 (8192) | AL @8192 | BH @16384 (20480) | BL @36864
// M_s (phase-1 epilogue, 40960 B) lives at 188416 = chunk3's B region.
// GEMM geometry: 512 thr, 16 warps (4M x 4N), warp tile 16x40, acc 20 regs.
// ---------------------------------------------------------------------------
#define CHB 57344
#define SG_TOT (4*CHB)      // 229376
#define MS_OFF (3*CHB + 16384)

__device__ __forceinline__ uint32_t swz(uint32_t base, int row, int col16) {
    return base + (uint32_t)row * 128 + (uint32_t)((col16 ^ (row & 7)) << 4);
}

#define GEMM_MAINLOOP(mb0)                                                     \
    _Pragma("unroll")                                                          \
    for (int c = 0; c < 4; c++) {                                              \
        MBAR_WAIT((mb0) + c * 8, 0);                                           \
        uint32_t cb = sb + c * CHB;                                            \
        _Pragma("unroll")                                                      \
        for (int ks = 0; ks < 4; ks++) {                                       \
            uint32_t ah[4], al[4], bh[5][2], bl[5][2];                         \
            int arow = warp_m * 16 + a_row_l;                                  \
            int ac = (ks << 1) | a_c16_l;                                      \
            ldsm4(ah[0], ah[1], ah[2], ah[3], swz(cb + 0, arow, ac));          \
            ldsm4(al[0], al[1], al[2], al[3], swz(cb + 8192, arow, ac));       \
            int bc = (ks << 1) | b_c16_l;                                      \
            _Pragma("unroll")                                                  \
            for (int p = 0; p < 5; p++) {                                      \
                int brow = warp_n * 40 + p * 8 + b_row_l;                      \
                ldsm2(bh[p][0], bh[p][1], swz(cb + 16384, brow, bc));          \
                ldsm2(bl[p][0], bl[p][1], swz(cb + 36864, brow, bc));          \
            }                                                                  \
            _Pragma("unroll")                                                  \
            for (int p = 0; p < 5; p++) {                                      \
                mma16816(acc[p], ah, bh[p]);                                   \
                mma16816(acc[p], ah, bl[p]);                                   \
                mma16816(acc[p], al, bh[p]);                                   \
            }                                                                  \
        }                                                                      \
    }

// s-GEMM epilogue: write partials, rendezvous, fused squash. (device inline)
__device__ __forceinline__ void sgemm_epilogue(
    float (*acc)[4], float* __restrict__ out, int t,
    int bx, int by, int tid, int lane, int warp_m, int warp_n) {
    float* po = g_part_s + (size_t)by * (BATCH * NDIM);
    int r_l = lane >> 2, c_l = (lane & 3) * 2;
    int row = bx * 64 + warp_m * 16 + r_l;
    #pragma unroll
    for (int p = 0; p < 5; p++) {
        int col = warp_n * 40 + p * 8 + c_l;
        *(float2*)(po + (size_t)row * NDIM + col) = make_float2(acc[p][0], acc[p][1]);
        *(float2*)(po + (size_t)(row + 8) * NDIM + col) = make_float2(acc[p][2], acc[p][3]);
    }

    __threadfence();
    __syncthreads();
    if (tid == 0) {
        atomicAdd(&g_cnt[bx], 1);
        int tgt = SPLITS_S * (t + 1);
        while (atomicAdd(&g_cnt[bx], 0) < tgt) __nanosleep(20);
    }
    __syncthreads();

    int n  = (by < 28) ? 18 : 17;
    int g0 = (by < 28) ? by * 18 : 28 * 18 + (by - 28) * 17;
    int gl = tid >> 4;
    int u  = tid & 15;
    bool act = gl < n;
    int idx = bx * 10240 + (g0 + gl) * 16 + u;
    float s = 0.f;
    if (act) {
        float a0 = 0.f, a1 = 0.f, a2 = 0.f, a3 = 0.f;
        #pragma unroll
        for (int sp = 0; sp < SPLITS_S; sp += 4) {
            a0 += __ldcg(&g_part_s[(size_t)(sp + 0) * (BATCH * NDIM) + idx]);
            a1 += __ldcg(&g_part_s[(size_t)(sp + 1) * (BATCH * NDIM) + idx]);
            a2 += __ldcg(&g_part_s[(size_t)(sp + 2) * (BATCH * NDIM) + idx]);
            a3 += __ldcg(&g_part_s[(size_t)(sp + 3) * (BATCH * NDIM) + idx]);
        }
        s = (a0 + a1) + (a2 + a3);
    }
    float sq = s * s;
    sq += __shfl_xor_sync(0xffffffffu, sq, 8);
    sq += __shfl_xor_sync(0xffffffffu, sq, 4);
    sq += __shfl_xor_sync(0xffffffffu, sq, 2);
    sq += __shfl_xor_sync(0xffffffffu, sq, 1);
    if (act) {
        float scale = sq / ((1.0f + sq) * sqrtf(sq + 1e-9f));
        float v = s * scale;
        if (t == 2) {
            out[idx] = v;
        } else {
            int b = idx / NDIM;
            int ou = idx - b * NDIM;
            int col = b & 63;
            uint32_t off = (uint32_t)bx * 20480 + ou * 128
                         + (((col >> 3) ^ (ou & 7)) << 4) + (col & 7) * 2;
            __nv_bfloat16 h, l;
            split_bf16(v, h, l);
            *(unsigned short*)(g_vT2_hi + off) = __bfloat16_as_ushort(h);
            *(unsigned short*)(g_vT2_lo + off) = __bfloat16_as_ushort(l);
        }
    }
}

// ---------------------------------------------------------------------------
// Standalone s-GEMM(0) + squash. grid (4, 36), 512 threads.
// ---------------------------------------------------------------------------
__global__ void __launch_bounds__(512, 1)
gemm_s0(float* __restrict__ out) {
    extern __shared__ char sm[];
    __shared__ __align__(8) uint64_t mbar[4];
    uint32_t sb = smem_to_u32(sm);
    uint32_t mb0 = smem_to_u32(mbar);
    int tid = threadIdx.x, lane = tid & 31, wid = tid >> 5;
    int warp_m = wid & 3, warp_n = wid >> 2;
    int bx = blockIdx.x, by = blockIdx.y;
    int chunk0 = by * 4;

    if (tid == 0) {
        #pragma unroll
        for (int i = 0; i < 4; i++) MBAR_INIT(mb0 + i * 8, 1);
    }
    __syncthreads();
    if (tid == 0) {
        #pragma unroll
        for (int c = 0; c < 4; c++) {
            uint32_t m = mb0 + c * 8;
            uint32_t cb = sb + c * CHB;
            int ch = chunk0 + c;
            MBAR_EXPECT(m, CHB);
            bulkcp(cb + 0,     g_A_hi + ((size_t)ch * 4 + bx) * 8192, 8192, m);
            bulkcp(cb + 8192,  g_A_lo + ((size_t)ch * 4 + bx) * 8192, 8192, m);
            bulkcp(cb + 16384, g_Bt_hi + (size_t)ch * 20480, 20480, m);
            bulkcp(cb + 36864, g_Bt_lo + (size_t)ch * 20480, 20480, m);
        }
    }

    float acc[5][4];
    #pragma unroll
    for (int p = 0; p < 5; p++)
        #pragma unroll
        for (int r = 0; r < 4; r++) acc[p][r] = 0.f;

    int a_row_l = ((lane >> 3) & 1) * 8 + (lane & 7);
    int a_c16_l = lane >> 4;
    int b_row_l = lane & 7;
    int b_c16_l = (lane >> 3) & 1;

    GEMM_MAINLOOP(mb0);
    sgemm_epilogue(acc, out, 0, bx, by, tid, lane, warp_m, warp_n);
}

// ---------------------------------------------------------------------------
// Fused kernel: phase 1 = M-GEMM(t-1) + b-update + Wc(t) (chunk == cta),
// then per-chunk flags gate phase 2 = s-GEMM(t) + squash.
// grid 144 (cta -> bx=cta&3, by=cta>>2), 512 threads.
// ---------------------------------------------------------------------------
__global__ void __launch_bounds__(512, 1)
fused_iter(const float* __restrict__ W, float* __restrict__ out, int t) {
    extern __shared__ char sm[];
    __shared__ __align__(8) uint64_t mbar[8];
    __shared__ float c_s[8][10];
    uint32_t sb = smem_to_u32(sm);
    uint32_t mb0 = smem_to_u32(mbar);
    int tid = threadIdx.x, lane = tid & 31, wid = tid >> 5;
    int warp_m = wid & 3, warp_n = wid >> 2;
    int cta = blockIdx.x;
    int tm1 = t - 1;

    if (tid == 0) {
        #pragma unroll
        for (int i = 0; i < 8; i++) MBAR_INIT(mb0 + i * 8, 1);
    }
    __syncthreads();
    // ---- phase 1 loads: M-GEMM operands ----
    if (tid == 0) {
        #pragma unroll
        for (int c = 0; c < 4; c++) {
            uint32_t m = mb0 + c * 8;
            uint32_t cb = sb + c * CHB;
            MBAR_EXPECT(m, CHB);
            bulkcp(cb + 0,     g_AT_hi + ((size_t)c * NCHUNK + cta) * 8192, 8192, m);
            bulkcp(cb + 8192,  g_AT_lo + ((size_t)c * NCHUNK + cta) * 8192, 8192, m);
            bulkcp(cb + 16384, g_vT2_hi + (size_t)c * 20480, 20480, m);
            bulkcp(cb + 36864, g_vT2_lo + (size_t)c * 20480, 20480, m);
        }
    }

    float acc[5][4];
    #pragma unroll
    for (int p = 0; p < 5; p++)
        #pragma unroll
        for (int r = 0; r < 4; r++) acc[p][r] = 0.f;

    int a_row_l = ((lane >> 3) & 1) * 8 + (lane & 7);
    int a_c16_l = lane >> 4;
    int b_row_l = lane & 7;
    int b_c16_l = (lane >> 3) & 1;

    GEMM_MAINLOOP(mb0);            // M-GEMM

    // ---- stage M tile [64][160] at MS_OFF (chunk3 B region) ----
    __syncthreads();               // all ldsm reads of staging done
    float* M_s = (float*)(sm + MS_OFF);
    {
        int r_l = lane >> 2, c_l = (lane & 3) * 2;
        int row = warp_m * 16 + r_l;
        #pragma unroll
        for (int p = 0; p < 5; p++) {
            int col = warp_n * 40 + p * 8 + c_l;
            *(float2*)(M_s + row * NDIM + col) = make_float2(acc[p][0], acc[p][1]);
            *(float2*)(M_s + (row + 8) * NDIM + col) = make_float2(acc[p][2], acc[p][3]);
        }
    }
    __syncthreads();

    // ---- issue phase-2 A loads early (regions disjoint from M_s) ----
    int bx = cta & 3, by = cta >> 2;
    int chunk0 = by * 4;
    if (tid == 0) {
        #pragma unroll
        for (int c = 0; c < 4; c++) {
            uint32_t m = mb0 + (4 + c) * 8;
            uint32_t cb = sb + c * CHB;
            int ch = chunk0 + c;
            MBAR_EXPECT(m, CHB);   // A (16384) now + B (40960) later
            bulkcp(cb + 0,    g_A_hi + ((size_t)ch * 4 + bx) * 8192, 8192, m);
            bulkcp(cb + 8192, g_A_lo + ((size_t)ch * 4 + bx) * 8192, 8192, m);
        }
    }

    // ---- b-update: delta[i,o] = (1/B) sum_{k,u} W[i,o,u,k]*M[i8+k][o16+u] ----
    #pragma unroll
    for (int ee = 0; ee < 5; ee++) {
        int e = wid * 5 + ee;
        int i_rel = e / 10, o = e - i_rel * 10;
        int i = cta * 8 + i_rel;
        float sum = 0.f;
        #pragma unroll
        for (int j = 0; j < 4; j++) {
            int f = lane + (j << 5);
            int k = f >> 4, u = f & 15;
            sum = fmaf(W[(size_t)i * 1280 + (o << 7) + (u << 3) + k],
                       M_s[(i_rel * 8 + k) * NDIM + o * 16 + u], sum);
        }
        #pragma unroll
        for (int off = 16; off; off >>= 1)
            sum += __shfl_xor_sync(0xffffffffu, sum, off);
        if (lane == 0) {
            float d = sum * (1.0f / (float)BATCH);
            int gw = i * OUTCH + o;
            g_b[gw] = (tm1 == 0) ? d : (g_b[gw] + d);
        }
    }
    __syncthreads();

    // ---- Wc(t) for chunk cta ----
    if (tid < 8) {
        int i = cta * 8 + tid;
        float bv[OUTCH], m = -1e30f;
        #pragma unroll
        for (int o = 0; o < OUTCH; o++) {
            bv[o] = g_b[i * OUTCH + o];
            m = fmaxf(m, bv[o]);
        }
        float sum = 0.f;
        #pragma unroll
        for (int o = 0; o < OUTCH; o++) { bv[o] = expf(bv[o] - m); sum += bv[o]; }
        float inv = 1.0f / sum;
        #pragma unroll
        for (int o = 0; o < OUTCH; o++) c_s[tid][o] = bv[o] * inv;
    }
    __syncthreads();
    wc_body<512>(W, cta, c_s, tid);
    __syncthreads();               // all wc stores + M_s reads complete

    // ---- flag own chunk; wait for this K-split's 4 producer chunks;
    //      then issue phase-2 B loads (overwrites M_s region: safe now) ----
    if (tid == 0) {
        asm volatile("fence.proxy.async;" ::: "memory");
        __threadfence();
        atomicAdd(&g_flag[cta], 1);
        #pragma unroll
        for (int c = 0; c < 4; c++) {
            int ch = chunk0 + c;
            while (atomicAdd(&g_flag[ch], 0) < t) __nanosleep(20);
        }
        #pragma unroll
        for (int c = 0; c < 4; c++) {
            uint32_t m = mb0 + (4 + c) * 8;
            uint32_t cb = sb + c * CHB;
            int ch = chunk0 + c;
            bulkcp(cb + 16384, g_Bt_hi + (size_t)ch * 20480, 20480, m);
            bulkcp(cb + 36864, g_Bt_lo + (size_t)ch * 20480, 20480, m);
        }
    }

    // ---- phase 2: s-GEMM(t) + squash ----
    #pragma unroll
    for (int p = 0; p < 5; p++)
        #pragma unroll
        for (int r = 0; r < 4; r++) acc[p][r] = 0.f;

    GEMM_MAINLOOP(mb0 + 32);       // mbar[4..7]
    sgemm_epilogue(acc, out, t, bx, by, tid, lane, warp_m, warp_n);
}

// ---------------------------------------------------------------------------
extern "C" void kernel_launch(void* const* d_in, const int* in_sizes, int n_in,
                              void* d_out, int out_size) {
    const float* inp = (const float*)d_in[0];  // [256,1152,8]
    const float* W   = (const float*)d_in[1];  // [1152,10,16,8]
    float* out = (float*)d_out;                // [256,10,16]

    cudaFuncSetAttribute(gemm_s0, cudaFuncAttributeMaxDynamicSharedMemorySize, SG_TOT);
    cudaFuncSetAttribute(fused_iter, cudaFuncAttributeMaxDynamicSharedMemorySize, SG_TOT);

    conv_inp<<<dim3(NCHUNK, 4), 256>>>(inp, W);       // + Wc(0) + resets
    gemm_s0<<<dim3(4, SPLITS_S), 512, SG_TOT>>>(out); // s-GEMM(0) + squash
    fused_iter<<<NCHUNK, 512, SG_TOT>>>(W, out, 1);   // M(0)+Wc(1) -> s(1)+squash
    fused_iter<<<NCHUNK, 512, SG_TOT>>>(W, out, 2);   // M(1)+Wc(2) -> s(2)+out
}